// round 2
// baseline (speedup 1.0000x reference)
#include <cuda_runtime.h>
#include <cuda_bf16.h>

#define N_NODES 50000
#define E_EDGES 1600000

// ---------------- scratch (device globals; no allocation allowed) ----------------
__device__ int   g_count[N_NODES];          // in-degree (int)
__device__ int   g_rowstart[N_NODES + 1];   // CSR row offsets (by dst)
__device__ int   g_cursor[N_NODES];         // fill cursors
__device__ int   g_srclist[E_EDGES];        // CSR: src ids bucketed by dst
__device__ float g_y2[N_NODES * 32];        // h1 @ W2_l^T (pre-aggregation, folded)
__device__ float g_r2[N_NODES * 32];        // h1 @ W2_r^T (self term, layer 2)
__device__ int   g_is64;                    // edge_index dtype flag

// ---------------- packed f32x2 helpers ----------------
__device__ __forceinline__ unsigned long long pack2(float lo, float hi) {
    unsigned long long r;
    asm("mov.b64 %0, {%1, %2};" : "=l"(r) : "f"(lo), "f"(hi));
    return r;
}
__device__ __forceinline__ float2 unpack2(unsigned long long v) {
    float2 f;
    asm("mov.b64 {%0, %1}, %2;" : "=f"(f.x), "=f"(f.y) : "l"(v));
    return f;
}
__device__ __forceinline__ unsigned long long ffma2(unsigned long long a,
                                                    unsigned long long b,
                                                    unsigned long long c) {
    unsigned long long d;
    asm("fma.rn.f32x2 %0, %1, %2, %3;" : "=l"(d) : "l"(a), "l"(b), "l"(c));
    return d;
}
__device__ __forceinline__ unsigned long long fadd2(unsigned long long a,
                                                    unsigned long long b) {
    unsigned long long d;
    asm("add.rn.f32x2 %0, %1, %2;" : "=l"(d) : "l"(a), "l"(b));
    return d;
}

// ---------------- dtype detection (int64 vs int32 edge_index) ----------------
__global__ void detect_dtype_k(const long long* __restrict__ ei) {
    if (threadIdx.x == 0 && blockIdx.x == 0) {
        int ok = 1;
        for (int i = 0; i < 64; i++) {
            long long v = ei[i];
            if (v < 0 || v >= N_NODES) { ok = 0; break; }
        }
        g_is64 = ok;
    }
}

// ---------------- zero degree counters ----------------
__global__ void zerocnt_k() {
    int i = blockIdx.x * blockDim.x + threadIdx.x;
    if (i < N_NODES) g_count[i] = 0;
}

// ---------------- histogram of dst ----------------
__global__ void hist_k(const void* __restrict__ ei) {
    int e = blockIdx.x * blockDim.x + threadIdx.x;
    if (e >= E_EDGES) return;
    int dst;
    if (g_is64) dst = (int)((const long long*)ei)[E_EDGES + e];
    else        dst = ((const int*)ei)[E_EDGES + e];
    atomicAdd(&g_count[dst], 1);
}

// ---------------- single-block exclusive scan over 50000 counts ----------------
__global__ void scan_k() {
    __shared__ int sm[1024];
    const int CH = 49;  // 1024 * 49 = 50176 >= 50000
    int t = threadIdx.x;
    int base = t * CH;
    int s = 0;
    for (int i = 0; i < CH; i++) {
        int idx = base + i;
        if (idx < N_NODES) s += g_count[idx];
    }
    sm[t] = s;
    __syncthreads();
    for (int st = 1; st < 1024; st <<= 1) {
        int v = sm[t];
        int a = (t >= st) ? sm[t - st] : 0;
        __syncthreads();
        sm[t] = v + a;
        __syncthreads();
    }
    int off = sm[t] - s;  // exclusive prefix of this thread's chunk
    for (int i = 0; i < CH; i++) {
        int idx = base + i;
        if (idx < N_NODES) {
            g_rowstart[idx] = off;
            g_cursor[idx]   = off;
            off += g_count[idx];
        }
    }
    if (t == 1023) g_rowstart[N_NODES] = sm[1023];
}

// ---------------- bucket fill: srclist grouped by dst ----------------
__global__ void fill_k(const void* __restrict__ ei) {
    int e = blockIdx.x * blockDim.x + threadIdx.x;
    if (e >= E_EDGES) return;
    int src, dst;
    if (g_is64) {
        const long long* p = (const long long*)ei;
        src = (int)p[e];
        dst = (int)p[E_EDGES + e];
    } else {
        const int* p = (const int*)ei;
        src = p[e];
        dst = p[E_EDGES + e];
    }
    int pos = atomicAdd(&g_cursor[dst], 1);
    g_srclist[pos] = src;
}

// ---------------- fused: gather x + layer1 dense + layer2 pre-projection ----------------
// One warp per node. Lane owns output channels (lane, lane+32) packed into f32x2.
// Phase 1: h1 = relu((sum x[src])/deg @ W1l^T + b1 + x @ W1r^T)
// Phase 2: y2 = h1 @ W2l^T ; r2 = h1 @ W2r^T (lane owns {y2[lane], r2[lane]} packed)
__global__ void __launch_bounds__(256) fused1_k(
        const float* __restrict__ x,
        const float* __restrict__ W1l, const float* __restrict__ b1,
        const float* __restrict__ W1r,
        const float* __restrict__ W2l, const float* __restrict__ W2r) {
    __shared__ ulonglong2 W4s[64 * 32];            // [k][o]: {wl_o,wl_o32 | wr_o,wr_o32}
    __shared__ unsigned long long W2s[64 * 32];    // [k][o]: {W2l[o][k], W2r[o][k]}
    __shared__ ulonglong2 axs[8][64];              // per warp: [c]: {a,a | x,x}

    int tid = threadIdx.x;
    for (int i = tid; i < 64 * 32; i += 256) {
        int k = i >> 5, o = i & 31;
        float wl0 = W1l[o * 64 + k],        wl1 = W1l[(o + 32) * 64 + k];
        float wr0 = W1r[o * 64 + k],        wr1 = W1r[(o + 32) * 64 + k];
        W4s[i] = make_ulonglong2(pack2(wl0, wl1), pack2(wr0, wr1));
        W2s[i] = pack2(W2l[o * 64 + k], W2r[o * 64 + k]);
    }
    __syncthreads();

    int w = tid >> 5, lane = tid & 31;
    int wg = blockIdx.x * 8 + w;

    for (int node = wg; node < N_NODES; node += 4736) {
        int start = g_rowstart[node], end = g_rowstart[node + 1];

        // ---- gather-sum of x[src] over this node's in-edges ----
        float aLo = 0.0f, aHi = 0.0f;
        int i = start;
        for (; i + 4 <= end; i += 4) {
            int s0 = __ldg(&g_srclist[i]),     s1 = __ldg(&g_srclist[i + 1]);
            int s2 = __ldg(&g_srclist[i + 2]), s3 = __ldg(&g_srclist[i + 3]);
            float v0 = __ldg(x + (size_t)s0 * 64 + lane);
            float u0 = __ldg(x + (size_t)s0 * 64 + lane + 32);
            float v1 = __ldg(x + (size_t)s1 * 64 + lane);
            float u1 = __ldg(x + (size_t)s1 * 64 + lane + 32);
            float v2 = __ldg(x + (size_t)s2 * 64 + lane);
            float u2 = __ldg(x + (size_t)s2 * 64 + lane + 32);
            float v3 = __ldg(x + (size_t)s3 * 64 + lane);
            float u3 = __ldg(x + (size_t)s3 * 64 + lane + 32);
            aLo += (v0 + v1) + (v2 + v3);
            aHi += (u0 + u1) + (u2 + u3);
        }
        for (; i < end; i++) {
            int s0 = __ldg(&g_srclist[i]);
            aLo += __ldg(x + (size_t)s0 * 64 + lane);
            aHi += __ldg(x + (size_t)s0 * 64 + lane + 32);
        }
        float invd = 1.0f / fmaxf((float)(end - start), 1.0f);
        aLo *= invd; aHi *= invd;
        float xLo = __ldg(x + (size_t)node * 64 + lane);
        float xHi = __ldg(x + (size_t)node * 64 + lane + 32);

        __syncwarp();  // previous iteration's axs reads done
        axs[w][lane]      = make_ulonglong2(pack2(aLo, aLo), pack2(xLo, xLo));
        axs[w][lane + 32] = make_ulonglong2(pack2(aHi, aHi), pack2(xHi, xHi));
        __syncwarp();

        // ---- phase 1: dense GEMV, packed over (lane, lane+32) ----
        unsigned long long acc0 = pack2(__ldg(b1 + lane), __ldg(b1 + lane + 32));
        unsigned long long acc1 = 0ull;
        #pragma unroll
        for (int k = 0; k < 64; k += 2) {
            ulonglong2 ax0 = axs[w][k];
            ulonglong2 w0  = W4s[k * 32 + lane];
            acc0 = ffma2(ax0.x, w0.x, acc0);
            acc0 = ffma2(ax0.y, w0.y, acc0);
            ulonglong2 ax1 = axs[w][k + 1];
            ulonglong2 w1  = W4s[(k + 1) * 32 + lane];
            acc1 = ffma2(ax1.x, w1.x, acc1);
            acc1 = ffma2(ax1.y, w1.y, acc1);
        }
        float2 h  = unpack2(fadd2(acc0, acc1));
        float hLo = fmaxf(h.x, 0.0f);
        float hHi = fmaxf(h.y, 0.0f);

        // ---- phase 2: {y2, r2} packed per lane, h broadcast via shfl ----
        unsigned long long y0 = 0ull, y1 = 0ull;
        #pragma unroll
        for (int k = 0; k < 32; k += 2) {
            float ha = __shfl_sync(0xFFFFFFFFu, hLo, k);
            y0 = ffma2(pack2(ha, ha), W2s[k * 32 + lane], y0);
            float hb = __shfl_sync(0xFFFFFFFFu, hLo, k + 1);
            y1 = ffma2(pack2(hb, hb), W2s[(k + 1) * 32 + lane], y1);
        }
        #pragma unroll
        for (int k = 32; k < 64; k += 2) {
            float ha = __shfl_sync(0xFFFFFFFFu, hHi, k - 32);
            y0 = ffma2(pack2(ha, ha), W2s[k * 32 + lane], y0);
            float hb = __shfl_sync(0xFFFFFFFFu, hHi, k + 1 - 32);
            y1 = ffma2(pack2(hb, hb), W2s[(k + 1) * 32 + lane], y1);
        }
        float2 yr = unpack2(fadd2(y0, y1));
        g_y2[(size_t)node * 32 + lane] = yr.x;
        g_r2[(size_t)node * 32 + lane] = yr.y;
    }
}

// ---------------- fused: gather y2 + final layer ----------------
// One warp per node; lane = channel 0..31.
__global__ void __launch_bounds__(256) fused2_k(
        const float* __restrict__ b2, const float* __restrict__ Wlin,
        const float* __restrict__ blin, float* __restrict__ out) {
    int tid = threadIdx.x;
    int w = tid >> 5, lane = tid & 31;
    int wg = blockIdx.x * 8 + w;
    float b2v = __ldg(b2 + lane);
    float wlv = __ldg(Wlin + lane);
    float blv = __ldg(blin);

    for (int node = wg; node < N_NODES; node += 4736) {
        int start = g_rowstart[node], end = g_rowstart[node + 1];
        float a = 0.0f;
        int i = start;
        for (; i + 4 <= end; i += 4) {
            int s0 = __ldg(&g_srclist[i]),     s1 = __ldg(&g_srclist[i + 1]);
            int s2 = __ldg(&g_srclist[i + 2]), s3 = __ldg(&g_srclist[i + 3]);
            float v0 = __ldg(&g_y2[(size_t)s0 * 32 + lane]);
            float v1 = __ldg(&g_y2[(size_t)s1 * 32 + lane]);
            float v2 = __ldg(&g_y2[(size_t)s2 * 32 + lane]);
            float v3 = __ldg(&g_y2[(size_t)s3 * 32 + lane]);
            a += (v0 + v1) + (v2 + v3);
        }
        for (; i < end; i++) {
            a += __ldg(&g_y2[(size_t)__ldg(&g_srclist[i]) * 32 + lane]);
        }
        float invd = 1.0f / fmaxf((float)(end - start), 1.0f);
        float v = a * invd + b2v + g_r2[(size_t)node * 32 + lane];
        v = fmaxf(v, 0.0f) * wlv;
        #pragma unroll
        for (int s = 16; s; s >>= 1) v += __shfl_xor_sync(0xFFFFFFFFu, v, s);
        if (lane == 0) out[node] = v + blv;
    }
}

// ---------------- launch ----------------
extern "C" void kernel_launch(void* const* d_in, const int* in_sizes, int n_in,
                              void* d_out, int out_size) {
    const float* x    = (const float*)d_in[0];
    const void*  ei   = d_in[1];
    const float* W1l  = (const float*)d_in[2];
    const float* b1   = (const float*)d_in[3];
    const float* W1r  = (const float*)d_in[4];
    const float* W2l  = (const float*)d_in[5];
    const float* b2   = (const float*)d_in[6];
    const float* W2r  = (const float*)d_in[7];
    const float* Wlin = (const float*)d_in[8];
    const float* blin = (const float*)d_in[9];
    float* out = (float*)d_out;

    detect_dtype_k<<<1, 1>>>((const long long*)ei);
    zerocnt_k<<<(N_NODES + 255) / 256, 256>>>();
    hist_k<<<(E_EDGES + 255) / 256, 256>>>(ei);
    scan_k<<<1, 1024>>>();
    fill_k<<<(E_EDGES + 255) / 256, 256>>>(ei);
    fused1_k<<<592, 256>>>(x, W1l, b1, W1r, W2l, W2r);
    fused2_k<<<592, 256>>>(b2, Wlin, blin, out);
}

// round 3
// speedup vs baseline: 1.3731x; 1.3731x over previous
#include <cuda_runtime.h>
#include <cuda_bf16.h>

#define N_NODES 50000
#define E_EDGES 1600000
#define SCAN_BLOCKS 196   // 196 * 256 = 50176 >= 50000

// ---------------- scratch (device globals; no allocation allowed) ----------------
__device__ int   g_count[N_NODES];          // in-degree (int)
__device__ int   g_rowstart[N_NODES + 1];   // CSR row offsets (by dst)
__device__ int   g_cursor[N_NODES];         // fill cursors
__device__ int   g_srclist[E_EDGES];        // CSR: src ids bucketed by dst
__device__ int   g_blocksum[SCAN_BLOCKS];   // scan partials
__device__ int   g_blockoff[SCAN_BLOCKS];   // scan block offsets
__device__ float g_y2[N_NODES * 32];        // h1 @ W2_l^T (pre-aggregation, folded)
__device__ float g_r2[N_NODES * 32];        // h1 @ W2_r^T (self term, layer 2)
__device__ int   g_is64;                    // edge_index dtype flag

// ---------------- packed f32x2 helpers ----------------
__device__ __forceinline__ unsigned long long pack2(float lo, float hi) {
    unsigned long long r;
    asm("mov.b64 %0, {%1, %2};" : "=l"(r) : "f"(lo), "f"(hi));
    return r;
}
__device__ __forceinline__ float2 unpack2(unsigned long long v) {
    float2 f;
    asm("mov.b64 {%0, %1}, %2;" : "=f"(f.x), "=f"(f.y) : "l"(v));
    return f;
}
__device__ __forceinline__ unsigned long long ffma2(unsigned long long a,
                                                    unsigned long long b,
                                                    unsigned long long c) {
    unsigned long long d;
    asm("fma.rn.f32x2 %0, %1, %2, %3;" : "=l"(d) : "l"(a), "l"(b), "l"(c));
    return d;
}
__device__ __forceinline__ unsigned long long fadd2(unsigned long long a,
                                                    unsigned long long b) {
    unsigned long long d;
    asm("add.rn.f32x2 %0, %1, %2;" : "=l"(d) : "l"(a), "l"(b));
    return d;
}

// ---------------- dtype detection (int64 vs int32 edge_index) ----------------
__global__ void detect_dtype_k(const long long* __restrict__ ei) {
    if (threadIdx.x == 0 && blockIdx.x == 0) {
        int ok = 1;
        for (int i = 0; i < 64; i++) {
            long long v = ei[i];
            if (v < 0 || v >= N_NODES) { ok = 0; break; }
        }
        g_is64 = ok;
    }
}

// ---------------- zero degree counters ----------------
__global__ void zerocnt_k() {
    int i = blockIdx.x * blockDim.x + threadIdx.x;
    if (i < N_NODES) g_count[i] = 0;
}

// ---------------- histogram of dst ----------------
__global__ void hist_k(const void* __restrict__ ei) {
    int e = blockIdx.x * blockDim.x + threadIdx.x;
    if (e >= E_EDGES) return;
    int dst;
    if (g_is64) dst = (int)((const long long*)ei)[E_EDGES + e];
    else        dst = ((const int*)ei)[E_EDGES + e];
    atomicAdd(&g_count[dst], 1);
}

// ---------------- parallel scan, stage 1: per-block sums ----------------
__global__ void blocksum_k() {
    __shared__ int sm[256];
    int t = threadIdx.x;
    int idx = blockIdx.x * 256 + t;
    sm[t] = (idx < N_NODES) ? g_count[idx] : 0;
    __syncthreads();
    #pragma unroll
    for (int s = 128; s; s >>= 1) {
        if (t < s) sm[t] += sm[t + s];
        __syncthreads();
    }
    if (t == 0) g_blocksum[blockIdx.x] = sm[0];
}

// ---------------- parallel scan, stage 2: scan block sums (1 small block) ----------------
__global__ void scanblocks_k() {
    __shared__ int sm[256];
    int t = threadIdx.x;
    int v = (t < SCAN_BLOCKS) ? g_blocksum[t] : 0;
    sm[t] = v;
    __syncthreads();
    #pragma unroll
    for (int st = 1; st < 256; st <<= 1) {
        int a = (t >= st) ? sm[t - st] : 0;
        __syncthreads();
        sm[t] += a;
        __syncthreads();
    }
    if (t < SCAN_BLOCKS) g_blockoff[t] = sm[t] - v;   // exclusive
    if (t == 255) g_rowstart[N_NODES] = sm[255];
}

// ---------------- parallel scan, stage 3: in-block scans + offset ----------------
__global__ void scanlocal_k() {
    __shared__ int sm[256];
    int t = threadIdx.x;
    int idx = blockIdx.x * 256 + t;
    int v = (idx < N_NODES) ? g_count[idx] : 0;
    sm[t] = v;
    __syncthreads();
    #pragma unroll
    for (int st = 1; st < 256; st <<= 1) {
        int a = (t >= st) ? sm[t - st] : 0;
        __syncthreads();
        sm[t] += a;
        __syncthreads();
    }
    if (idx < N_NODES) {
        int excl = sm[t] - v + g_blockoff[blockIdx.x];
        g_rowstart[idx] = excl;
        g_cursor[idx]   = excl;
    }
}

// ---------------- bucket fill: srclist grouped by dst ----------------
__global__ void fill_k(const void* __restrict__ ei) {
    int e = blockIdx.x * blockDim.x + threadIdx.x;
    if (e >= E_EDGES) return;
    int src, dst;
    if (g_is64) {
        const long long* p = (const long long*)ei;
        src = (int)p[e];
        dst = (int)p[E_EDGES + e];
    } else {
        const int* p = (const int*)ei;
        src = p[e];
        dst = p[E_EDGES + e];
    }
    int pos = atomicAdd(&g_cursor[dst], 1);
    g_srclist[pos] = src;
}

// ---------------- fused: gather x + layer1 dense + layer2 pre-projection ----------------
// One warp per node. Lane owns channel pair (2*lane, 2*lane+1) packed as f32x2.
// Phase 1: h1 = relu((sum x[src])/deg @ W1l^T + b1 + x @ W1r^T)
// Phase 2: y2 = h1 @ W2l^T ; r2 = h1 @ W2r^T (lane owns {y2[lane], r2[lane]})
__global__ void __launch_bounds__(256) fused1_k(
        const float* __restrict__ x,
        const float* __restrict__ W1l, const float* __restrict__ b1,
        const float* __restrict__ W1r,
        const float* __restrict__ W2l, const float* __restrict__ W2r) {
    __shared__ ulonglong2 W4s[64 * 32];            // [k][o]: {wl_2o,wl_2o+1 | wr_2o,wr_2o+1}
    __shared__ unsigned long long W2s[64 * 32];    // [k][o]: {W2l[o][k], W2r[o][k]}
    __shared__ ulonglong2 axs[8][64];              // per warp: [k]: {a,a | x,x}

    int tid = threadIdx.x;
    for (int i = tid; i < 64 * 32; i += 256) {
        int k = i >> 5, o = i & 31;
        W4s[i] = make_ulonglong2(
            pack2(W1l[(2 * o) * 64 + k], W1l[(2 * o + 1) * 64 + k]),
            pack2(W1r[(2 * o) * 64 + k], W1r[(2 * o + 1) * 64 + k]));
        W2s[i] = pack2(W2l[o * 64 + k], W2r[o * 64 + k]);
    }
    __syncthreads();

    int w = tid >> 5, lane = tid & 31;
    unsigned long long b1v = pack2(__ldg(b1 + 2 * lane), __ldg(b1 + 2 * lane + 1));
    int stride = gridDim.x * 8;

    for (int node = blockIdx.x * 8 + w; node < N_NODES; node += stride) {
        int start = g_rowstart[node], end = g_rowstart[node + 1];

        // ---- gather-sum of x[src] over this node's in-edges (float2 per lane) ----
        float aLo = 0.0f, aHi = 0.0f;
        int i = start;
        for (; i + 8 <= end; i += 8) {
            int s0 = __ldg(&g_srclist[i]),     s1 = __ldg(&g_srclist[i + 1]);
            int s2 = __ldg(&g_srclist[i + 2]), s3 = __ldg(&g_srclist[i + 3]);
            int s4 = __ldg(&g_srclist[i + 4]), s5 = __ldg(&g_srclist[i + 5]);
            int s6 = __ldg(&g_srclist[i + 6]), s7 = __ldg(&g_srclist[i + 7]);
            float2 v0 = __ldg((const float2*)(x + (size_t)s0 * 64) + lane);
            float2 v1 = __ldg((const float2*)(x + (size_t)s1 * 64) + lane);
            float2 v2 = __ldg((const float2*)(x + (size_t)s2 * 64) + lane);
            float2 v3 = __ldg((const float2*)(x + (size_t)s3 * 64) + lane);
            float2 v4 = __ldg((const float2*)(x + (size_t)s4 * 64) + lane);
            float2 v5 = __ldg((const float2*)(x + (size_t)s5 * 64) + lane);
            float2 v6 = __ldg((const float2*)(x + (size_t)s6 * 64) + lane);
            float2 v7 = __ldg((const float2*)(x + (size_t)s7 * 64) + lane);
            aLo += ((v0.x + v1.x) + (v2.x + v3.x)) + ((v4.x + v5.x) + (v6.x + v7.x));
            aHi += ((v0.y + v1.y) + (v2.y + v3.y)) + ((v4.y + v5.y) + (v6.y + v7.y));
        }
        for (; i < end; i++) {
            int s0 = __ldg(&g_srclist[i]);
            float2 v = __ldg((const float2*)(x + (size_t)s0 * 64) + lane);
            aLo += v.x; aHi += v.y;
        }
        float invd = 1.0f / fmaxf((float)(end - start), 1.0f);
        aLo *= invd; aHi *= invd;
        float2 xv = __ldg((const float2*)(x + (size_t)node * 64) + lane);

        __syncwarp();  // previous iteration's axs reads done
        axs[w][2 * lane]     = make_ulonglong2(pack2(aLo, aLo), pack2(xv.x, xv.x));
        axs[w][2 * lane + 1] = make_ulonglong2(pack2(aHi, aHi), pack2(xv.y, xv.y));
        __syncwarp();

        // ---- phase 1: dense GEMV, packed over (2*lane, 2*lane+1) ----
        unsigned long long acc0 = b1v;
        unsigned long long acc1 = 0ull;
        #pragma unroll
        for (int k = 0; k < 64; k += 2) {
            ulonglong2 ax0 = axs[w][k];
            ulonglong2 w0  = W4s[k * 32 + lane];
            acc0 = ffma2(ax0.x, w0.x, acc0);
            acc0 = ffma2(ax0.y, w0.y, acc0);
            ulonglong2 ax1 = axs[w][k + 1];
            ulonglong2 w1  = W4s[(k + 1) * 32 + lane];
            acc1 = ffma2(ax1.x, w1.x, acc1);
            acc1 = ffma2(ax1.y, w1.y, acc1);
        }
        float2 h  = unpack2(fadd2(acc0, acc1));
        float hLo = fmaxf(h.x, 0.0f);   // channel 2*lane
        float hHi = fmaxf(h.y, 0.0f);   // channel 2*lane + 1

        // ---- phase 2: {y2, r2} packed per lane, h broadcast via shfl ----
        unsigned long long y0 = 0ull, y1 = 0ull;
        #pragma unroll
        for (int k = 0; k < 64; k += 2) {
            float ha = __shfl_sync(0xFFFFFFFFu, hLo, k >> 1);   // h[k], k even
            y0 = ffma2(pack2(ha, ha), W2s[k * 32 + lane], y0);
            float hb = __shfl_sync(0xFFFFFFFFu, hHi, k >> 1);   // h[k+1], odd
            y1 = ffma2(pack2(hb, hb), W2s[(k + 1) * 32 + lane], y1);
        }
        float2 yr = unpack2(fadd2(y0, y1));
        g_y2[(size_t)node * 32 + lane] = yr.x;
        g_r2[(size_t)node * 32 + lane] = yr.y;
    }
}

// ---------------- fused: gather y2 + final layer ----------------
// One warp per node; lane = channel 0..31.
__global__ void __launch_bounds__(256) fused2_k(
        const float* __restrict__ b2, const float* __restrict__ Wlin,
        const float* __restrict__ blin, float* __restrict__ out) {
    int tid = threadIdx.x;
    int w = tid >> 5, lane = tid & 31;
    float b2v = __ldg(b2 + lane);
    float wlv = __ldg(Wlin + lane);
    float blv = __ldg(blin);
    int stride = gridDim.x * 8;

    for (int node = blockIdx.x * 8 + w; node < N_NODES; node += stride) {
        int start = g_rowstart[node], end = g_rowstart[node + 1];
        float a = 0.0f;
        int i = start;
        for (; i + 8 <= end; i += 8) {
            int s0 = __ldg(&g_srclist[i]),     s1 = __ldg(&g_srclist[i + 1]);
            int s2 = __ldg(&g_srclist[i + 2]), s3 = __ldg(&g_srclist[i + 3]);
            int s4 = __ldg(&g_srclist[i + 4]), s5 = __ldg(&g_srclist[i + 5]);
            int s6 = __ldg(&g_srclist[i + 6]), s7 = __ldg(&g_srclist[i + 7]);
            float v0 = __ldg(&g_y2[(size_t)s0 * 32 + lane]);
            float v1 = __ldg(&g_y2[(size_t)s1 * 32 + lane]);
            float v2 = __ldg(&g_y2[(size_t)s2 * 32 + lane]);
            float v3 = __ldg(&g_y2[(size_t)s3 * 32 + lane]);
            float v4 = __ldg(&g_y2[(size_t)s4 * 32 + lane]);
            float v5 = __ldg(&g_y2[(size_t)s5 * 32 + lane]);
            float v6 = __ldg(&g_y2[(size_t)s6 * 32 + lane]);
            float v7 = __ldg(&g_y2[(size_t)s7 * 32 + lane]);
            a += ((v0 + v1) + (v2 + v3)) + ((v4 + v5) + (v6 + v7));
        }
        for (; i < end; i++) {
            a += __ldg(&g_y2[(size_t)__ldg(&g_srclist[i]) * 32 + lane]);
        }
        float invd = 1.0f / fmaxf((float)(end - start), 1.0f);
        float v = a * invd + b2v + g_r2[(size_t)node * 32 + lane];
        v = fmaxf(v, 0.0f) * wlv;
        #pragma unroll
        for (int s = 16; s; s >>= 1) v += __shfl_xor_sync(0xFFFFFFFFu, v, s);
        if (lane == 0) out[node] = v + blv;
    }
}

// ---------------- launch ----------------
extern "C" void kernel_launch(void* const* d_in, const int* in_sizes, int n_in,
                              void* d_out, int out_size) {
    const float* x    = (const float*)d_in[0];
    const void*  ei   = d_in[1];
    const float* W1l  = (const float*)d_in[2];
    const float* b1   = (const float*)d_in[3];
    const float* W1r  = (const float*)d_in[4];
    const float* W2l  = (const float*)d_in[5];
    const float* b2   = (const float*)d_in[6];
    const float* W2r  = (const float*)d_in[7];
    const float* Wlin = (const float*)d_in[8];
    const float* blin = (const float*)d_in[9];
    float* out = (float*)d_out;

    detect_dtype_k<<<1, 1>>>((const long long*)ei);
    zerocnt_k<<<(N_NODES + 255) / 256, 256>>>();
    hist_k<<<(E_EDGES + 255) / 256, 256>>>(ei);
    blocksum_k<<<SCAN_BLOCKS, 256>>>();
    scanblocks_k<<<1, 256>>>();
    scanlocal_k<<<SCAN_BLOCKS, 256>>>();
    fill_k<<<(E_EDGES + 255) / 256, 256>>>(ei);
    fused1_k<<<444, 256>>>(x, W1l, b1, W1r, W2l, W2r);
    fused2_k<<<592, 256>>>(b2, Wlin, blin, out);
}

// round 4
// speedup vs baseline: 1.4689x; 1.0698x over previous
#include <cuda_runtime.h>
#include <cuda_bf16.h>

#define N_NODES 50000
#define E_EDGES 1600000
#define SCAN_BLOCKS 196   // 196 * 256 = 50176 >= 50000
#define N_TILES 12500     // 50000 / 4 exactly

// ---------------- scratch (device globals; no allocation allowed) ----------------
__device__ int   g_count[N_NODES];          // in-degree (int)
__device__ int   g_rowstart[N_NODES + 1];   // CSR row offsets (by dst)
__device__ int   g_cursor[N_NODES];         // fill cursors
__device__ int   g_srclist[E_EDGES];        // CSR: src ids bucketed by dst
__device__ int   g_blocksum[SCAN_BLOCKS];   // scan partials
__device__ float g_y2[N_NODES * 32];        // h1 @ W2_l^T (pre-aggregation, folded)
__device__ float g_r2[N_NODES * 32];        // h1 @ W2_r^T (self term, layer 2)
__device__ int   g_is64;                    // edge_index dtype flag

// ---------------- packed f32x2 helpers ----------------
__device__ __forceinline__ unsigned long long pack2(float lo, float hi) {
    unsigned long long r;
    asm("mov.b64 %0, {%1, %2};" : "=l"(r) : "f"(lo), "f"(hi));
    return r;
}
__device__ __forceinline__ float2 unpack2(unsigned long long v) {
    float2 f;
    asm("mov.b64 {%0, %1}, %2;" : "=f"(f.x), "=f"(f.y) : "l"(v));
    return f;
}
__device__ __forceinline__ unsigned long long ffma2(unsigned long long a,
                                                    unsigned long long b,
                                                    unsigned long long c) {
    unsigned long long d;
    asm("fma.rn.f32x2 %0, %1, %2, %3;" : "=l"(d) : "l"(a), "l"(b), "l"(c));
    return d;
}
__device__ __forceinline__ unsigned long long fadd2(unsigned long long a,
                                                    unsigned long long b) {
    unsigned long long d;
    asm("add.rn.f32x2 %0, %1, %2;" : "=l"(d) : "l"(a), "l"(b));
    return d;
}

// ---------------- init: zero counters + parallel dtype detection ----------------
__global__ void init_k(const long long* __restrict__ ei) {
    int i = blockIdx.x * blockDim.x + threadIdx.x;
    if (i < N_NODES) g_count[i] = 0;
    if (blockIdx.x == 0) {
        if (threadIdx.x == 0) g_is64 = 1;
        __syncthreads();
        if (threadIdx.x < 64) {
            long long v = ei[threadIdx.x];
            if (v < 0 || v >= N_NODES) atomicAnd(&g_is64, 0);
        }
    }
}

// ---------------- histogram of dst ----------------
__global__ void hist_k(const void* __restrict__ ei) {
    int e = blockIdx.x * blockDim.x + threadIdx.x;
    if (e >= E_EDGES) return;
    int dst;
    if (g_is64) dst = (int)((const long long*)ei)[E_EDGES + e];
    else        dst = ((const int*)ei)[E_EDGES + e];
    atomicAdd(&g_count[dst], 1);
}

// ---------------- scan stage 1: per-block sums ----------------
__global__ void blocksum_k() {
    __shared__ int sm[256];
    int t = threadIdx.x;
    int idx = blockIdx.x * 256 + t;
    sm[t] = (idx < N_NODES) ? g_count[idx] : 0;
    __syncthreads();
    #pragma unroll
    for (int s = 128; s; s >>= 1) {
        if (t < s) sm[t] += sm[t + s];
        __syncthreads();
    }
    if (t == 0) g_blocksum[blockIdx.x] = sm[0];
}

// ---------------- scan stage 2: every block scans blocksums redundantly + local scan ----------------
__global__ void scan_k2() {
    __shared__ int bs[256];
    __shared__ int sm[256];
    int t = threadIdx.x;
    bs[t] = (t < SCAN_BLOCKS) ? g_blocksum[t] : 0;
    __syncthreads();
    #pragma unroll
    for (int st = 1; st < 256; st <<= 1) {
        int a = (t >= st) ? bs[t - st] : 0;
        __syncthreads();
        bs[t] += a;
        __syncthreads();
    }
    int blockoff = (blockIdx.x > 0) ? bs[blockIdx.x - 1] : 0;
    if (blockIdx.x == 0 && t == 0) g_rowstart[N_NODES] = bs[SCAN_BLOCKS - 1];

    int idx = blockIdx.x * 256 + t;
    int v = (idx < N_NODES) ? g_count[idx] : 0;
    sm[t] = v;
    __syncthreads();
    #pragma unroll
    for (int st = 1; st < 256; st <<= 1) {
        int a = (t >= st) ? sm[t - st] : 0;
        __syncthreads();
        sm[t] += a;
        __syncthreads();
    }
    if (idx < N_NODES) {
        int excl = sm[t] - v + blockoff;
        g_rowstart[idx] = excl;
        g_cursor[idx]   = excl;
    }
}

// ---------------- bucket fill: srclist grouped by dst ----------------
__global__ void fill_k(const void* __restrict__ ei) {
    int e = blockIdx.x * blockDim.x + threadIdx.x;
    if (e >= E_EDGES) return;
    int src, dst;
    if (g_is64) {
        const long long* p = (const long long*)ei;
        src = (int)p[e];
        dst = (int)p[E_EDGES + e];
    } else {
        const int* p = (const int*)ei;
        src = p[e];
        dst = p[E_EDGES + e];
    }
    int pos = atomicAdd(&g_cursor[dst], 1);
    g_srclist[pos] = src;
}

// ---------------- fused: gather x + layer1 dense + layer2 pre-projection ----------------
// One warp per 4-node tile. Lane owns channel pair (2*lane, 2*lane+1) packed f32x2.
// Weight LDS128 shared across the 4 nodes (amortizes smem crossbar 4x).
// smem (dynamic 64KB): W4s 32KB | W2s 16KB | axs 16KB
__global__ void __launch_bounds__(128) fused1_k(
        const float* __restrict__ x,
        const float* __restrict__ W1l, const float* __restrict__ b1,
        const float* __restrict__ W1r,
        const float* __restrict__ W2l, const float* __restrict__ W2r) {
    extern __shared__ unsigned char sraw[];
    ulonglong2*         W4s = (ulonglong2*)sraw;                          // [k*32+o]
    unsigned long long* W2s = (unsigned long long*)(sraw + 32768);        // [k*32+o]
    ulonglong2*         axs = (ulonglong2*)(sraw + 49152);                // [warp][j][k]

    int tid = threadIdx.x;
    for (int i = tid; i < 2048; i += 128) {
        int k = i >> 5, o = i & 31;
        W4s[i] = make_ulonglong2(
            pack2(W1l[(2 * o) * 64 + k], W1l[(2 * o + 1) * 64 + k]),
            pack2(W1r[(2 * o) * 64 + k], W1r[(2 * o + 1) * 64 + k]));
        W2s[i] = pack2(W2l[o * 64 + k], W2r[o * 64 + k]);
    }
    __syncthreads();

    int w = tid >> 5, lane = tid & 31;
    unsigned long long b1v = pack2(__ldg(b1 + 2 * lane), __ldg(b1 + 2 * lane + 1));
    ulonglong2* axw = axs + w * 256;      // [j*64 + k]
    int nwarps = gridDim.x * 4;

    for (int t = blockIdx.x * 4 + w; t < N_TILES; t += nwarps) {
        int n0 = t * 4;
        __syncwarp();   // previous tile's axs reads complete

        // ---- gather 4 nodes' neighbor sums ----
        #pragma unroll
        for (int j = 0; j < 4; j++) {
            int node = n0 + j;
            int start = g_rowstart[node], end = g_rowstart[node + 1];
            float aLo = 0.0f, aHi = 0.0f;
            int i = start;
            for (; i + 8 <= end; i += 8) {
                int s0 = __ldg(&g_srclist[i]),     s1 = __ldg(&g_srclist[i + 1]);
                int s2 = __ldg(&g_srclist[i + 2]), s3 = __ldg(&g_srclist[i + 3]);
                int s4 = __ldg(&g_srclist[i + 4]), s5 = __ldg(&g_srclist[i + 5]);
                int s6 = __ldg(&g_srclist[i + 6]), s7 = __ldg(&g_srclist[i + 7]);
                float2 v0 = __ldg((const float2*)(x + (size_t)s0 * 64) + lane);
                float2 v1 = __ldg((const float2*)(x + (size_t)s1 * 64) + lane);
                float2 v2 = __ldg((const float2*)(x + (size_t)s2 * 64) + lane);
                float2 v3 = __ldg((const float2*)(x + (size_t)s3 * 64) + lane);
                float2 v4 = __ldg((const float2*)(x + (size_t)s4 * 64) + lane);
                float2 v5 = __ldg((const float2*)(x + (size_t)s5 * 64) + lane);
                float2 v6 = __ldg((const float2*)(x + (size_t)s6 * 64) + lane);
                float2 v7 = __ldg((const float2*)(x + (size_t)s7 * 64) + lane);
                aLo += ((v0.x + v1.x) + (v2.x + v3.x)) + ((v4.x + v5.x) + (v6.x + v7.x));
                aHi += ((v0.y + v1.y) + (v2.y + v3.y)) + ((v4.y + v5.y) + (v6.y + v7.y));
            }
            for (; i < end; i++) {
                int s0 = __ldg(&g_srclist[i]);
                float2 v = __ldg((const float2*)(x + (size_t)s0 * 64) + lane);
                aLo += v.x; aHi += v.y;
            }
            float invd = 1.0f / fmaxf((float)(end - start), 1.0f);
            aLo *= invd; aHi *= invd;
            float2 xv = __ldg((const float2*)(x + (size_t)node * 64) + lane);
            // write splatted operands once (reused 64x each as uniform broadcasts)
            axw[j * 64 + 2 * lane]     = make_ulonglong2(pack2(aLo, aLo), pack2(xv.x, xv.x));
            axw[j * 64 + 2 * lane + 1] = make_ulonglong2(pack2(aHi, aHi), pack2(xv.y, xv.y));
        }
        __syncwarp();

        // ---- phase 1: dense GEMV, weight load shared by 4 nodes ----
        unsigned long long a0[4], a1[4];
        #pragma unroll
        for (int j = 0; j < 4; j++) { a0[j] = b1v; a1[j] = 0ull; }
        #pragma unroll 16
        for (int k = 0; k < 64; k++) {
            ulonglong2 wv = W4s[k * 32 + lane];
            #pragma unroll
            for (int j = 0; j < 4; j++) {
                ulonglong2 ax = axw[j * 64 + k];   // uniform broadcast
                a0[j] = ffma2(ax.x, wv.x, a0[j]);
                a1[j] = ffma2(ax.y, wv.y, a1[j]);
            }
        }
        float hL[4], hH[4];
        #pragma unroll
        for (int j = 0; j < 4; j++) {
            float2 h = unpack2(fadd2(a0[j], a1[j]));
            hL[j] = fmaxf(h.x, 0.0f);   // channel 2*lane
            hH[j] = fmaxf(h.y, 0.0f);   // channel 2*lane+1
        }

        // ---- phase 2: {y2, r2} per lane; W2 load shared by 4 nodes; h via shfl ----
        unsigned long long y0[4], y1[4];
        #pragma unroll
        for (int j = 0; j < 4; j++) { y0[j] = 0ull; y1[j] = 0ull; }
        #pragma unroll 8
        for (int k2 = 0; k2 < 32; k2++) {
            unsigned long long wA = W2s[(2 * k2) * 32 + lane];
            unsigned long long wB = W2s[(2 * k2 + 1) * 32 + lane];
            #pragma unroll
            for (int j = 0; j < 4; j++) {
                float ha = __shfl_sync(0xFFFFFFFFu, hL[j], k2);
                y0[j] = ffma2(pack2(ha, ha), wA, y0[j]);
                float hb = __shfl_sync(0xFFFFFFFFu, hH[j], k2);
                y1[j] = ffma2(pack2(hb, hb), wB, y1[j]);
            }
        }
        #pragma unroll
        for (int j = 0; j < 4; j++) {
            float2 yr = unpack2(fadd2(y0[j], y1[j]));
            int node = n0 + j;
            g_y2[(size_t)node * 32 + lane] = yr.x;
            g_r2[(size_t)node * 32 + lane] = yr.y;
        }
    }
}

// ---------------- fused: gather y2 + final layer ----------------
__global__ void __launch_bounds__(256) fused2_k(
        const float* __restrict__ b2, const float* __restrict__ Wlin,
        const float* __restrict__ blin, float* __restrict__ out) {
    int tid = threadIdx.x;
    int w = tid >> 5, lane = tid & 31;
    float b2v = __ldg(b2 + lane);
    float wlv = __ldg(Wlin + lane);
    float blv = __ldg(blin);
    int stride = gridDim.x * 8;

    for (int node = blockIdx.x * 8 + w; node < N_NODES; node += stride) {
        int start = g_rowstart[node], end = g_rowstart[node + 1];
        float a = 0.0f;
        int i = start;
        for (; i + 8 <= end; i += 8) {
            int s0 = __ldg(&g_srclist[i]),     s1 = __ldg(&g_srclist[i + 1]);
            int s2 = __ldg(&g_srclist[i + 2]), s3 = __ldg(&g_srclist[i + 3]);
            int s4 = __ldg(&g_srclist[i + 4]), s5 = __ldg(&g_srclist[i + 5]);
            int s6 = __ldg(&g_srclist[i + 6]), s7 = __ldg(&g_srclist[i + 7]);
            float v0 = __ldg(&g_y2[(size_t)s0 * 32 + lane]);
            float v1 = __ldg(&g_y2[(size_t)s1 * 32 + lane]);
            float v2 = __ldg(&g_y2[(size_t)s2 * 32 + lane]);
            float v3 = __ldg(&g_y2[(size_t)s3 * 32 + lane]);
            float v4 = __ldg(&g_y2[(size_t)s4 * 32 + lane]);
            float v5 = __ldg(&g_y2[(size_t)s5 * 32 + lane]);
            float v6 = __ldg(&g_y2[(size_t)s6 * 32 + lane]);
            float v7 = __ldg(&g_y2[(size_t)s7 * 32 + lane]);
            a += ((v0 + v1) + (v2 + v3)) + ((v4 + v5) + (v6 + v7));
        }
        for (; i < end; i++) {
            a += __ldg(&g_y2[(size_t)__ldg(&g_srclist[i]) * 32 + lane]);
        }
        float invd = 1.0f / fmaxf((float)(end - start), 1.0f);
        float v = a * invd + b2v + g_r2[(size_t)node * 32 + lane];
        v = fmaxf(v, 0.0f) * wlv;
        #pragma unroll
        for (int s = 16; s; s >>= 1) v += __shfl_xor_sync(0xFFFFFFFFu, v, s);
        if (lane == 0) out[node] = v + blv;
    }
}

// ---------------- launch ----------------
extern "C" void kernel_launch(void* const* d_in, const int* in_sizes, int n_in,
                              void* d_out, int out_size) {
    const float* x    = (const float*)d_in[0];
    const void*  ei   = d_in[1];
    const float* W1l  = (const float*)d_in[2];
    const float* b1   = (const float*)d_in[3];
    const float* W1r  = (const float*)d_in[4];
    const float* W2l  = (const float*)d_in[5];
    const float* b2   = (const float*)d_in[6];
    const float* W2r  = (const float*)d_in[7];
    const float* Wlin = (const float*)d_in[8];
    const float* blin = (const float*)d_in[9];
    float* out = (float*)d_out;

    static int attr_done = 0;
    if (!attr_done) {
        cudaFuncSetAttribute(fused1_k, cudaFuncAttributeMaxDynamicSharedMemorySize, 65536);
        attr_done = 1;
    }

    init_k<<<(N_NODES + 255) / 256, 256>>>((const long long*)ei);
    hist_k<<<(E_EDGES + 255) / 256, 256>>>(ei);
    blocksum_k<<<SCAN_BLOCKS, 256>>>();
    scan_k2<<<SCAN_BLOCKS, 256>>>();
    fill_k<<<(E_EDGES + 255) / 256, 256>>>(ei);
    fused1_k<<<444, 128, 65536>>>(x, W1l, b1, W1r, W2l, W2r);
    fused2_k<<<592, 256>>>(b2, Wlin, blin, out);
}

// round 5
// speedup vs baseline: 1.6397x; 1.1163x over previous
#include <cuda_runtime.h>
#include <cuda_bf16.h>
#include <cuda_fp16.h>

#define N_NODES 50000
#define E_EDGES 1600000
#define SCAN_BLOCKS 196   // 196 * 256 = 50176 >= 50000
#define N_TILES 12500     // 50000 / 4 exactly

// ---------------- scratch (device globals; no allocation allowed) ----------------
__device__ int     g_count[N_NODES];          // in-degree (int)
__device__ int     g_rowstart[N_NODES + 1];   // CSR row offsets (by dst)
__device__ int     g_cursor[N_NODES];         // fill cursors
__device__ int     g_srclist[E_EDGES];        // CSR: src ids bucketed by dst
__device__ int     g_blocksum[SCAN_BLOCKS];   // scan partials
__device__ __half2 g_xh[N_NODES * 32];        // x in half2 (channel pairs)
__device__ __half2 g_y2h[N_NODES * 16];       // h1 @ W2_l^T in half2 (channel pairs)
__device__ float   g_r2[N_NODES * 32];        // h1 @ W2_r^T (self term, layer 2)
__device__ int     g_is64;                    // edge_index dtype flag

// ---------------- packed f32x2 helpers ----------------
__device__ __forceinline__ unsigned long long pack2(float lo, float hi) {
    unsigned long long r;
    asm("mov.b64 %0, {%1, %2};" : "=l"(r) : "f"(lo), "f"(hi));
    return r;
}
__device__ __forceinline__ float2 unpack2(unsigned long long v) {
    float2 f;
    asm("mov.b64 {%0, %1}, %2;" : "=f"(f.x), "=f"(f.y) : "l"(v));
    return f;
}
__device__ __forceinline__ unsigned long long ffma2(unsigned long long a,
                                                    unsigned long long b,
                                                    unsigned long long c) {
    unsigned long long d;
    asm("fma.rn.f32x2 %0, %1, %2, %3;" : "=l"(d) : "l"(a), "l"(b), "l"(c));
    return d;
}
__device__ __forceinline__ unsigned long long fadd2(unsigned long long a,
                                                    unsigned long long b) {
    unsigned long long d;
    asm("add.rn.f32x2 %0, %1, %2;" : "=l"(d) : "l"(a), "l"(b));
    return d;
}

// ---------------- init: zero counters + x->half2 conversion + dtype detection ----------------
__global__ void init_k(const float* __restrict__ x, const long long* __restrict__ ei) {
    int i = blockIdx.x * blockDim.x + threadIdx.x;
    if (i < N_NODES) g_count[i] = 0;
    if (i < N_NODES * 32) {
        float2 v = __ldg((const float2*)x + i);
        g_xh[i] = __float22half2_rn(v);
    }
    if (blockIdx.x == 0) {
        if (threadIdx.x == 0) g_is64 = 1;
        __syncthreads();
        if (threadIdx.x < 64) {
            long long v = ei[threadIdx.x];
            if (v < 0 || v >= N_NODES) atomicAnd(&g_is64, 0);
        }
    }
}

// ---------------- histogram of dst ----------------
__global__ void hist_k(const void* __restrict__ ei) {
    int e = blockIdx.x * blockDim.x + threadIdx.x;
    if (e >= E_EDGES) return;
    int dst;
    if (g_is64) dst = (int)((const long long*)ei)[E_EDGES + e];
    else        dst = ((const int*)ei)[E_EDGES + e];
    atomicAdd(&g_count[dst], 1);
}

// ---------------- scan stage 1: per-block sums ----------------
__global__ void blocksum_k() {
    __shared__ int sm[256];
    int t = threadIdx.x;
    int idx = blockIdx.x * 256 + t;
    sm[t] = (idx < N_NODES) ? g_count[idx] : 0;
    __syncthreads();
    #pragma unroll
    for (int s = 128; s; s >>= 1) {
        if (t < s) sm[t] += sm[t + s];
        __syncthreads();
    }
    if (t == 0) g_blocksum[blockIdx.x] = sm[0];
}

// ---------------- scan stage 2: redundant block-sum scan + local scan ----------------
__global__ void scan_k2() {
    __shared__ int bs[256];
    __shared__ int sm[256];
    int t = threadIdx.x;
    bs[t] = (t < SCAN_BLOCKS) ? g_blocksum[t] : 0;
    __syncthreads();
    #pragma unroll
    for (int st = 1; st < 256; st <<= 1) {
        int a = (t >= st) ? bs[t - st] : 0;
        __syncthreads();
        bs[t] += a;
        __syncthreads();
    }
    int blockoff = (blockIdx.x > 0) ? bs[blockIdx.x - 1] : 0;
    if (blockIdx.x == 0 && t == 0) g_rowstart[N_NODES] = bs[SCAN_BLOCKS - 1];

    int idx = blockIdx.x * 256 + t;
    int v = (idx < N_NODES) ? g_count[idx] : 0;
    sm[t] = v;
    __syncthreads();
    #pragma unroll
    for (int st = 1; st < 256; st <<= 1) {
        int a = (t >= st) ? sm[t - st] : 0;
        __syncthreads();
        sm[t] += a;
        __syncthreads();
    }
    if (idx < N_NODES) {
        int excl = sm[t] - v + blockoff;
        g_rowstart[idx] = excl;
        g_cursor[idx]   = excl;
    }
}

// ---------------- bucket fill: srclist grouped by dst ----------------
__global__ void fill_k(const void* __restrict__ ei) {
    int e = blockIdx.x * blockDim.x + threadIdx.x;
    if (e >= E_EDGES) return;
    int src, dst;
    if (g_is64) {
        const long long* p = (const long long*)ei;
        src = (int)p[e];
        dst = (int)p[E_EDGES + e];
    } else {
        const int* p = (const int*)ei;
        src = p[e];
        dst = p[E_EDGES + e];
    }
    int pos = atomicAdd(&g_cursor[dst], 1);
    g_srclist[pos] = src;
}

// ---------------- fused: gather x(half2) + layer1 dense + layer2 pre-projection ----------------
// One warp per 4-node tile. Lane owns channel pair (2*lane, 2*lane+1).
// smem (dynamic 80KB): W4s 32KB | W2s 16KB | axs 32KB (8 warps)
__global__ void __launch_bounds__(256) fused1_k(
        const float* __restrict__ x,
        const float* __restrict__ W1l, const float* __restrict__ b1,
        const float* __restrict__ W1r,
        const float* __restrict__ W2l, const float* __restrict__ W2r) {
    extern __shared__ unsigned char sraw[];
    ulonglong2*         W4s = (ulonglong2*)sraw;                          // [k*32+o]
    unsigned long long* W2s = (unsigned long long*)(sraw + 32768);        // [k*32+o]
    ulonglong2*         axs = (ulonglong2*)(sraw + 49152);                // [warp][j][k]

    int tid = threadIdx.x;
    for (int i = tid; i < 2048; i += 256) {
        int k = i >> 5, o = i & 31;
        W4s[i] = make_ulonglong2(
            pack2(W1l[(2 * o) * 64 + k], W1l[(2 * o + 1) * 64 + k]),
            pack2(W1r[(2 * o) * 64 + k], W1r[(2 * o + 1) * 64 + k]));
        W2s[i] = pack2(W2l[o * 64 + k], W2r[o * 64 + k]);
    }
    __syncthreads();

    int w = tid >> 5, lane = tid & 31;
    unsigned long long b1v = pack2(__ldg(b1 + 2 * lane), __ldg(b1 + 2 * lane + 1));
    ulonglong2* axw = axs + w * 256;      // [j*64 + k]
    int nwarps = gridDim.x * 8;

    for (int t = blockIdx.x * 8 + w; t < N_TILES; t += nwarps) {
        int n0 = t * 4;
        __syncwarp();   // previous tile's axs reads complete

        // ---- gather 4 nodes' neighbor sums (half2 rows, fp32 accumulation) ----
        #pragma unroll
        for (int j = 0; j < 4; j++) {
            int node = n0 + j;
            int start = g_rowstart[node], end = g_rowstart[node + 1];
            float aLo = 0.0f, aHi = 0.0f;
            int i = start;
            for (; i + 8 <= end; i += 8) {
                int s0 = __ldg(&g_srclist[i]),     s1 = __ldg(&g_srclist[i + 1]);
                int s2 = __ldg(&g_srclist[i + 2]), s3 = __ldg(&g_srclist[i + 3]);
                int s4 = __ldg(&g_srclist[i + 4]), s5 = __ldg(&g_srclist[i + 5]);
                int s6 = __ldg(&g_srclist[i + 6]), s7 = __ldg(&g_srclist[i + 7]);
                float2 v0 = __half22float2(g_xh[(size_t)s0 * 32 + lane]);
                float2 v1 = __half22float2(g_xh[(size_t)s1 * 32 + lane]);
                float2 v2 = __half22float2(g_xh[(size_t)s2 * 32 + lane]);
                float2 v3 = __half22float2(g_xh[(size_t)s3 * 32 + lane]);
                float2 v4 = __half22float2(g_xh[(size_t)s4 * 32 + lane]);
                float2 v5 = __half22float2(g_xh[(size_t)s5 * 32 + lane]);
                float2 v6 = __half22float2(g_xh[(size_t)s6 * 32 + lane]);
                float2 v7 = __half22float2(g_xh[(size_t)s7 * 32 + lane]);
                aLo += ((v0.x + v1.x) + (v2.x + v3.x)) + ((v4.x + v5.x) + (v6.x + v7.x));
                aHi += ((v0.y + v1.y) + (v2.y + v3.y)) + ((v4.y + v5.y) + (v6.y + v7.y));
            }
            for (; i < end; i++) {
                float2 v = __half22float2(g_xh[(size_t)__ldg(&g_srclist[i]) * 32 + lane]);
                aLo += v.x; aHi += v.y;
            }
            float invd = 1.0f / fmaxf((float)(end - start), 1.0f);
            aLo *= invd; aHi *= invd;
            float2 xv = __ldg((const float2*)(x + (size_t)node * 64) + lane);  // self fp32
            axw[j * 64 + 2 * lane]     = make_ulonglong2(pack2(aLo, aLo), pack2(xv.x, xv.x));
            axw[j * 64 + 2 * lane + 1] = make_ulonglong2(pack2(aHi, aHi), pack2(xv.y, xv.y));
        }
        __syncwarp();

        // ---- phase 1: dense GEMV, weight load shared by 4 nodes ----
        unsigned long long a0[4], a1[4];
        #pragma unroll
        for (int j = 0; j < 4; j++) { a0[j] = b1v; a1[j] = 0ull; }
        #pragma unroll 16
        for (int k = 0; k < 64; k++) {
            ulonglong2 wv = W4s[k * 32 + lane];
            #pragma unroll
            for (int j = 0; j < 4; j++) {
                ulonglong2 ax = axw[j * 64 + k];   // uniform broadcast
                a0[j] = ffma2(ax.x, wv.x, a0[j]);
                a1[j] = ffma2(ax.y, wv.y, a1[j]);
            }
        }
        float hL[4], hH[4];
        #pragma unroll
        for (int j = 0; j < 4; j++) {
            float2 h = unpack2(fadd2(a0[j], a1[j]));
            hL[j] = fmaxf(h.x, 0.0f);   // channel 2*lane
            hH[j] = fmaxf(h.y, 0.0f);   // channel 2*lane+1
        }

        // ---- phase 2: {y2, r2} per lane; W2 load shared by 4 nodes; h via shfl ----
        unsigned long long y0[4], y1[4];
        #pragma unroll
        for (int j = 0; j < 4; j++) { y0[j] = 0ull; y1[j] = 0ull; }
        #pragma unroll 8
        for (int k2 = 0; k2 < 32; k2++) {
            unsigned long long wA = W2s[(2 * k2) * 32 + lane];
            unsigned long long wB = W2s[(2 * k2 + 1) * 32 + lane];
            #pragma unroll
            for (int j = 0; j < 4; j++) {
                float ha = __shfl_sync(0xFFFFFFFFu, hL[j], k2);
                y0[j] = ffma2(pack2(ha, ha), wA, y0[j]);
                float hb = __shfl_sync(0xFFFFFFFFu, hH[j], k2);
                y1[j] = ffma2(pack2(hb, hb), wB, y1[j]);
            }
        }
        #pragma unroll
        for (int j = 0; j < 4; j++) {
            float2 yr = unpack2(fadd2(y0[j], y1[j]));   // {y2[lane], r2[lane]}
            int node = n0 + j;
            g_r2[(size_t)node * 32 + lane] = yr.y;
            float ynext = __shfl_down_sync(0xFFFFFFFFu, yr.x, 1);
            if ((lane & 1) == 0)
                g_y2h[(size_t)node * 16 + (lane >> 1)] = __floats2half2_rn(yr.x, ynext);
        }
    }
}

// ---------------- fused: gather y2(half2) + final layer ----------------
// One warp per node; 2 edges per step (lanes 0-15 edge A, 16-31 edge B);
// lane owns channel pair (2*l16, 2*l16+1).
__global__ void __launch_bounds__(256) fused2_k(
        const float* __restrict__ b2, const float* __restrict__ Wlin,
        const float* __restrict__ blin, float* __restrict__ out) {
    int tid = threadIdx.x;
    int w = tid >> 5, lane = tid & 31;
    int half = lane >> 4, l16 = lane & 15;
    float2 b2v = __ldg((const float2*)b2 + l16);
    float2 wlv = __ldg((const float2*)Wlin + l16);
    float blv = __ldg(blin);
    int stride = gridDim.x * 8;

    for (int node = blockIdx.x * 8 + w; node < N_NODES; node += stride) {
        int start = g_rowstart[node], end = g_rowstart[node + 1];
        float ax = 0.0f, ay = 0.0f;
        int i = start;
        for (; i + 8 <= end; i += 8) {
            int s0 = __ldg(&g_srclist[i + half]);
            int s1 = __ldg(&g_srclist[i + 2 + half]);
            int s2 = __ldg(&g_srclist[i + 4 + half]);
            int s3 = __ldg(&g_srclist[i + 6 + half]);
            float2 v0 = __half22float2(g_y2h[(size_t)s0 * 16 + l16]);
            float2 v1 = __half22float2(g_y2h[(size_t)s1 * 16 + l16]);
            float2 v2 = __half22float2(g_y2h[(size_t)s2 * 16 + l16]);
            float2 v3 = __half22float2(g_y2h[(size_t)s3 * 16 + l16]);
            ax += (v0.x + v1.x) + (v2.x + v3.x);
            ay += (v0.y + v1.y) + (v2.y + v3.y);
        }
        for (; i + 2 <= end; i += 2) {
            int s = __ldg(&g_srclist[i + half]);
            float2 v = __half22float2(g_y2h[(size_t)s * 16 + l16]);
            ax += v.x; ay += v.y;
        }
        if (i < end && half == 0) {
            int s = __ldg(&g_srclist[i]);
            float2 v = __half22float2(g_y2h[(size_t)s * 16 + l16]);
            ax += v.x; ay += v.y;
        }
        // combine the two half-warps
        ax += __shfl_xor_sync(0xFFFFFFFFu, ax, 16);
        ay += __shfl_xor_sync(0xFFFFFFFFu, ay, 16);

        float invd = 1.0f / fmaxf((float)(end - start), 1.0f);
        float2 r2v = __ldg((const float2*)(g_r2 + (size_t)node * 32) + l16);
        float vx = fmaxf(ax * invd + b2v.x + r2v.x, 0.0f) * wlv.x;
        float vy = fmaxf(ay * invd + b2v.y + r2v.y, 0.0f) * wlv.y;
        float dot = vx + vy;
        #pragma unroll
        for (int s = 8; s; s >>= 1) dot += __shfl_xor_sync(0xFFFFFFFFu, dot, s);
        if (lane == 0) out[node] = dot + blv;
    }
}

// ---------------- launch ----------------
extern "C" void kernel_launch(void* const* d_in, const int* in_sizes, int n_in,
                              void* d_out, int out_size) {
    const float* x    = (const float*)d_in[0];
    const void*  ei   = d_in[1];
    const float* W1l  = (const float*)d_in[2];
    const float* b1   = (const float*)d_in[3];
    const float* W1r  = (const float*)d_in[4];
    const float* W2l  = (const float*)d_in[5];
    const float* b2   = (const float*)d_in[6];
    const float* W2r  = (const float*)d_in[7];
    const float* Wlin = (const float*)d_in[8];
    const float* blin = (const float*)d_in[9];
    float* out = (float*)d_out;

    static int attr_done = 0;
    if (!attr_done) {
        cudaFuncSetAttribute(fused1_k, cudaFuncAttributeMaxDynamicSharedMemorySize, 81920);
        attr_done = 1;
    }

    init_k<<<(N_NODES * 32 + 255) / 256, 256>>>(x, (const long long*)ei);
    hist_k<<<(E_EDGES + 255) / 256, 256>>>(ei);
    blocksum_k<<<SCAN_BLOCKS, 256>>>();
    scan_k2<<<SCAN_BLOCKS, 256>>>();
    fill_k<<<(E_EDGES + 255) / 256, 256>>>(ei);
    fused1_k<<<296, 256, 81920>>>(x, W1l, b1, W1r, W2l, W2r);
    fused2_k<<<1184, 256>>>(b2, Wlin, blin, out);
}

// round 6
// speedup vs baseline: 1.6922x; 1.0320x over previous
#include <cuda_runtime.h>
#include <cuda_bf16.h>
#include <cuda_fp16.h>

#define N_NODES 50000
#define E_EDGES 1600000
#define SCAN_BLOCKS 196   // 196 * 256 = 50176 >= 50000
#define N_TILES 12500     // 50000 / 4 exactly

// ---------------- scratch (device globals; no allocation allowed) ----------------
__device__ int     g_count[N_NODES];          // in-degree (int)
__device__ int     g_rowstart[N_NODES + 1];   // CSR row offsets (by dst)
__device__ int     g_cursor[N_NODES];         // fill cursors
__device__ int     g_srclist[E_EDGES];        // CSR: src ids bucketed by dst
__device__ int     g_blocksum[SCAN_BLOCKS];   // scan partials
__device__ __half2 g_xh[N_NODES * 32];        // x in half2 (channel pairs)
__device__ __half2 g_y2h[N_NODES * 16];       // h1 @ W2_l^T in half2 (channel pairs)
__device__ float   g_r2[N_NODES * 32];        // h1 @ W2_r^T (self term, layer 2)
__device__ int     g_is64;                    // edge_index dtype flag

// ---------------- packed f32x2 helpers ----------------
__device__ __forceinline__ unsigned long long pack2(float lo, float hi) {
    unsigned long long r;
    asm("mov.b64 %0, {%1, %2};" : "=l"(r) : "f"(lo), "f"(hi));
    return r;
}
__device__ __forceinline__ float2 unpack2(unsigned long long v) {
    float2 f;
    asm("mov.b64 {%0, %1}, %2;" : "=f"(f.x), "=f"(f.y) : "l"(v));
    return f;
}
__device__ __forceinline__ unsigned long long ffma2(unsigned long long a,
                                                    unsigned long long b,
                                                    unsigned long long c) {
    unsigned long long d;
    asm("fma.rn.f32x2 %0, %1, %2, %3;" : "=l"(d) : "l"(a), "l"(b), "l"(c));
    return d;
}
__device__ __forceinline__ unsigned long long fadd2(unsigned long long a,
                                                    unsigned long long b) {
    unsigned long long d;
    asm("add.rn.f32x2 %0, %1, %2;" : "=l"(d) : "l"(a), "l"(b));
    return d;
}

// half2-pair (uint2) -> 4 floats accumulate
__device__ __forceinline__ void acc4(uint2 u, float& a0, float& a1, float& a2, float& a3) {
    float2 p0 = __half22float2(*(__half2*)&u.x);
    float2 p1 = __half22float2(*(__half2*)&u.y);
    a0 += p0.x; a1 += p0.y; a2 += p1.x; a3 += p1.y;
}

// ---------------- init: zero counters + x->half2 conversion + dtype detection ----------------
__global__ void init_k(const float* __restrict__ x, const long long* __restrict__ ei) {
    int i = blockIdx.x * blockDim.x + threadIdx.x;
    if (i < N_NODES) g_count[i] = 0;
    if (i < N_NODES * 32) {
        float2 v = __ldg((const float2*)x + i);
        g_xh[i] = __float22half2_rn(v);
    }
    if (blockIdx.x == 0) {
        if (threadIdx.x == 0) g_is64 = 1;
        __syncthreads();
        if (threadIdx.x < 64) {
            long long v = ei[threadIdx.x];
            if (v < 0 || v >= N_NODES) atomicAnd(&g_is64, 0);
        }
    }
}

// ---------------- histogram of dst (4 edges / thread, vectorized loads) ----------------
__global__ void hist_k(const void* __restrict__ ei) {
    int e = (blockIdx.x * blockDim.x + threadIdx.x) * 4;
    if (e >= E_EDGES) return;
    int d0, d1, d2, d3;
    if (g_is64) {
        const longlong2* p = (const longlong2*)((const long long*)ei + E_EDGES + e);
        longlong2 a = __ldg(p), b = __ldg(p + 1);
        d0 = (int)a.x; d1 = (int)a.y; d2 = (int)b.x; d3 = (int)b.y;
    } else {
        int4 a = __ldg((const int4*)((const int*)ei + E_EDGES + e));
        d0 = a.x; d1 = a.y; d2 = a.z; d3 = a.w;
    }
    atomicAdd(&g_count[d0], 1);
    atomicAdd(&g_count[d1], 1);
    atomicAdd(&g_count[d2], 1);
    atomicAdd(&g_count[d3], 1);
}

// ---------------- scan stage 1: per-block sums ----------------
__global__ void blocksum_k() {
    __shared__ int sm[256];
    int t = threadIdx.x;
    int idx = blockIdx.x * 256 + t;
    sm[t] = (idx < N_NODES) ? g_count[idx] : 0;
    __syncthreads();
    #pragma unroll
    for (int s = 128; s; s >>= 1) {
        if (t < s) sm[t] += sm[t + s];
        __syncthreads();
    }
    if (t == 0) g_blocksum[blockIdx.x] = sm[0];
}

// ---------------- scan stage 2: redundant block-sum scan + local scan ----------------
__global__ void scan_k2() {
    __shared__ int bs[256];
    __shared__ int sm[256];
    int t = threadIdx.x;
    bs[t] = (t < SCAN_BLOCKS) ? g_blocksum[t] : 0;
    __syncthreads();
    #pragma unroll
    for (int st = 1; st < 256; st <<= 1) {
        int a = (t >= st) ? bs[t - st] : 0;
        __syncthreads();
        bs[t] += a;
        __syncthreads();
    }
    int blockoff = (blockIdx.x > 0) ? bs[blockIdx.x - 1] : 0;
    if (blockIdx.x == 0 && t == 0) g_rowstart[N_NODES] = bs[SCAN_BLOCKS - 1];

    int idx = blockIdx.x * 256 + t;
    int v = (idx < N_NODES) ? g_count[idx] : 0;
    sm[t] = v;
    __syncthreads();
    #pragma unroll
    for (int st = 1; st < 256; st <<= 1) {
        int a = (t >= st) ? sm[t - st] : 0;
        __syncthreads();
        sm[t] += a;
        __syncthreads();
    }
    if (idx < N_NODES) {
        int excl = sm[t] - v + blockoff;
        g_rowstart[idx] = excl;
        g_cursor[idx]   = excl;
    }
}

// ---------------- bucket fill (4 edges / thread, vectorized loads) ----------------
__global__ void fill_k(const void* __restrict__ ei) {
    int e = (blockIdx.x * blockDim.x + threadIdx.x) * 4;
    if (e >= E_EDGES) return;
    int s0, s1, s2, s3, d0, d1, d2, d3;
    if (g_is64) {
        const longlong2* ps = (const longlong2*)((const long long*)ei + e);
        const longlong2* pd = (const longlong2*)((const long long*)ei + E_EDGES + e);
        longlong2 a = __ldg(ps), b = __ldg(ps + 1);
        longlong2 c = __ldg(pd), d = __ldg(pd + 1);
        s0 = (int)a.x; s1 = (int)a.y; s2 = (int)b.x; s3 = (int)b.y;
        d0 = (int)c.x; d1 = (int)c.y; d2 = (int)d.x; d3 = (int)d.y;
    } else {
        int4 a = __ldg((const int4*)((const int*)ei + e));
        int4 c = __ldg((const int4*)((const int*)ei + E_EDGES + e));
        s0 = a.x; s1 = a.y; s2 = a.z; s3 = a.w;
        d0 = c.x; d1 = c.y; d2 = c.z; d3 = c.w;
    }
    g_srclist[atomicAdd(&g_cursor[d0], 1)] = s0;
    g_srclist[atomicAdd(&g_cursor[d1], 1)] = s1;
    g_srclist[atomicAdd(&g_cursor[d2], 1)] = s2;
    g_srclist[atomicAdd(&g_cursor[d3], 1)] = s3;
}

// ---------------- fused: gather x(half2, 2 edges/step) + layer1 dense + layer2 pre ----------------
// One warp per 4-node tile. Gather: lanes 0-15 edge A, 16-31 edge B; lane owns
// channels 4*l16..4*l16+3 (uint2 = 2x half2). Dense: lane owns channel pair
// (2*lane, 2*lane+1) packed f32x2.
// smem (dynamic 80KB): W4s 32KB | W2s 16KB | axs 32KB (8 warps)
__global__ void __launch_bounds__(256) fused1_k(
        const float* __restrict__ x,
        const float* __restrict__ W1l, const float* __restrict__ b1,
        const float* __restrict__ W1r,
        const float* __restrict__ W2l, const float* __restrict__ W2r) {
    extern __shared__ unsigned char sraw[];
    ulonglong2*         W4s = (ulonglong2*)sraw;                          // [k*32+o]
    unsigned long long* W2s = (unsigned long long*)(sraw + 32768);        // [k*32+o]
    ulonglong2*         axs = (ulonglong2*)(sraw + 49152);                // [warp][j][k]

    int tid = threadIdx.x;
    for (int i = tid; i < 2048; i += 256) {
        int k = i >> 5, o = i & 31;
        W4s[i] = make_ulonglong2(
            pack2(W1l[(2 * o) * 64 + k], W1l[(2 * o + 1) * 64 + k]),
            pack2(W1r[(2 * o) * 64 + k], W1r[(2 * o + 1) * 64 + k]));
        W2s[i] = pack2(W2l[o * 64 + k], W2r[o * 64 + k]);
    }
    __syncthreads();

    int w = tid >> 5, lane = tid & 31;
    int half = lane >> 4, l16 = lane & 15;
    unsigned long long b1v = pack2(__ldg(b1 + 2 * lane), __ldg(b1 + 2 * lane + 1));
    ulonglong2* axw = axs + w * 256;      // [j*64 + k]
    const uint2* xh2 = (const uint2*)g_xh;  // row = 16 uint2
    int nwarps = gridDim.x * 8;

    for (int t = blockIdx.x * 8 + w; t < N_TILES; t += nwarps) {
        int n0 = t * 4;
        __syncwarp();   // previous tile's axs reads complete

        // ---- gather 4 nodes' neighbor sums (2 edges per warp-step) ----
        #pragma unroll
        for (int j = 0; j < 4; j++) {
            int node = n0 + j;
            int start = g_rowstart[node], end = g_rowstart[node + 1];
            float a0 = 0.0f, a1 = 0.0f, a2 = 0.0f, a3 = 0.0f;
            int i = start;
            for (; i + 8 <= end; i += 8) {
                int s0 = __ldg(&g_srclist[i + half]);
                int s1 = __ldg(&g_srclist[i + 2 + half]);
                int s2 = __ldg(&g_srclist[i + 4 + half]);
                int s3 = __ldg(&g_srclist[i + 6 + half]);
                uint2 u0 = __ldg(xh2 + (size_t)s0 * 16 + l16);
                uint2 u1 = __ldg(xh2 + (size_t)s1 * 16 + l16);
                uint2 u2 = __ldg(xh2 + (size_t)s2 * 16 + l16);
                uint2 u3 = __ldg(xh2 + (size_t)s3 * 16 + l16);
                acc4(u0, a0, a1, a2, a3);
                acc4(u1, a0, a1, a2, a3);
                acc4(u2, a0, a1, a2, a3);
                acc4(u3, a0, a1, a2, a3);
            }
            for (; i + 2 <= end; i += 2) {
                int s = __ldg(&g_srclist[i + half]);
                uint2 u = __ldg(xh2 + (size_t)s * 16 + l16);
                acc4(u, a0, a1, a2, a3);
            }
            if (i < end && half == 0) {
                int s = __ldg(&g_srclist[i]);
                uint2 u = __ldg(xh2 + (size_t)s * 16 + l16);
                acc4(u, a0, a1, a2, a3);
            }
            // combine the two half-warps
            a0 += __shfl_xor_sync(0xFFFFFFFFu, a0, 16);
            a1 += __shfl_xor_sync(0xFFFFFFFFu, a1, 16);
            a2 += __shfl_xor_sync(0xFFFFFFFFu, a2, 16);
            a3 += __shfl_xor_sync(0xFFFFFFFFu, a3, 16);

            float invd = 1.0f / fmaxf((float)(end - start), 1.0f);
            float4 xv = __ldg((const float4*)(x + (size_t)node * 64) + l16);  // self fp32
            if (half == 0) {
                axw[j * 64 + 4 * l16]     = make_ulonglong2(pack2(a0 * invd, a0 * invd),
                                                            pack2(xv.x, xv.x));
                axw[j * 64 + 4 * l16 + 1] = make_ulonglong2(pack2(a1 * invd, a1 * invd),
                                                            pack2(xv.y, xv.y));
            } else {
                axw[j * 64 + 4 * l16 + 2] = make_ulonglong2(pack2(a2 * invd, a2 * invd),
                                                            pack2(xv.z, xv.z));
                axw[j * 64 + 4 * l16 + 3] = make_ulonglong2(pack2(a3 * invd, a3 * invd),
                                                            pack2(xv.w, xv.w));
            }
        }
        __syncwarp();

        // ---- phase 1: dense GEMV, weight load shared by 4 nodes ----
        unsigned long long p0[4], p1[4];
        #pragma unroll
        for (int j = 0; j < 4; j++) { p0[j] = b1v; p1[j] = 0ull; }
        #pragma unroll 16
        for (int k = 0; k < 64; k++) {
            ulonglong2 wv = W4s[k * 32 + lane];
            #pragma unroll
            for (int j = 0; j < 4; j++) {
                ulonglong2 ax = axw[j * 64 + k];   // uniform broadcast
                p0[j] = ffma2(ax.x, wv.x, p0[j]);
                p1[j] = ffma2(ax.y, wv.y, p1[j]);
            }
        }
        float hL[4], hH[4];
        #pragma unroll
        for (int j = 0; j < 4; j++) {
            float2 h = unpack2(fadd2(p0[j], p1[j]));
            hL[j] = fmaxf(h.x, 0.0f);   // channel 2*lane
            hH[j] = fmaxf(h.y, 0.0f);   // channel 2*lane+1
        }

        // ---- phase 2: {y2, r2} per lane; W2 load shared by 4 nodes; h via shfl ----
        unsigned long long y0[4], y1[4];
        #pragma unroll
        for (int j = 0; j < 4; j++) { y0[j] = 0ull; y1[j] = 0ull; }
        #pragma unroll 8
        for (int k2 = 0; k2 < 32; k2++) {
            unsigned long long wA = W2s[(2 * k2) * 32 + lane];
            unsigned long long wB = W2s[(2 * k2 + 1) * 32 + lane];
            #pragma unroll
            for (int j = 0; j < 4; j++) {
                float ha = __shfl_sync(0xFFFFFFFFu, hL[j], k2);
                y0[j] = ffma2(pack2(ha, ha), wA, y0[j]);
                float hb = __shfl_sync(0xFFFFFFFFu, hH[j], k2);
                y1[j] = ffma2(pack2(hb, hb), wB, y1[j]);
            }
        }
        #pragma unroll
        for (int j = 0; j < 4; j++) {
            float2 yr = unpack2(fadd2(y0[j], y1[j]));   // {y2[lane], r2[lane]}
            int node = n0 + j;
            g_r2[(size_t)node * 32 + lane] = yr.y;
            float ynext = __shfl_down_sync(0xFFFFFFFFu, yr.x, 1);
            if ((lane & 1) == 0)
                g_y2h[(size_t)node * 16 + (lane >> 1)] = __floats2half2_rn(yr.x, ynext);
        }
    }
}

// ---------------- fused: gather y2(half2) + final layer ----------------
// One warp per node; 2 edges per step (lanes 0-15 edge A, 16-31 edge B);
// lane owns channel pair (2*l16, 2*l16+1).
__global__ void __launch_bounds__(256) fused2_k(
        const float* __restrict__ b2, const float* __restrict__ Wlin,
        const float* __restrict__ blin, float* __restrict__ out) {
    int tid = threadIdx.x;
    int w = tid >> 5, lane = tid & 31;
    int half = lane >> 4, l16 = lane & 15;
    float2 b2v = __ldg((const float2*)b2 + l16);
    float2 wlv = __ldg((const float2*)Wlin + l16);
    float blv = __ldg(blin);
    int stride = gridDim.x * 8;

    for (int node = blockIdx.x * 8 + w; node < N_NODES; node += stride) {
        int start = g_rowstart[node], end = g_rowstart[node + 1];
        float ax = 0.0f, ay = 0.0f;
        int i = start;
        for (; i + 8 <= end; i += 8) {
            int s0 = __ldg(&g_srclist[i + half]);
            int s1 = __ldg(&g_srclist[i + 2 + half]);
            int s2 = __ldg(&g_srclist[i + 4 + half]);
            int s3 = __ldg(&g_srclist[i + 6 + half]);
            float2 v0 = __half22float2(g_y2h[(size_t)s0 * 16 + l16]);
            float2 v1 = __half22float2(g_y2h[(size_t)s1 * 16 + l16]);
            float2 v2 = __half22float2(g_y2h[(size_t)s2 * 16 + l16]);
            float2 v3 = __half22float2(g_y2h[(size_t)s3 * 16 + l16]);
            ax += (v0.x + v1.x) + (v2.x + v3.x);
            ay += (v0.y + v1.y) + (v2.y + v3.y);
        }
        for (; i + 2 <= end; i += 2) {
            int s = __ldg(&g_srclist[i + half]);
            float2 v = __half22float2(g_y2h[(size_t)s * 16 + l16]);
            ax += v.x; ay += v.y;
        }
        if (i < end && half == 0) {
            int s = __ldg(&g_srclist[i]);
            float2 v = __half22float2(g_y2h[(size_t)s * 16 + l16]);
            ax += v.x; ay += v.y;
        }
        ax += __shfl_xor_sync(0xFFFFFFFFu, ax, 16);
        ay += __shfl_xor_sync(0xFFFFFFFFu, ay, 16);

        float invd = 1.0f / fmaxf((float)(end - start), 1.0f);
        float2 r2v = __ldg((const float2*)(g_r2 + (size_t)node * 32) + l16);
        float vx = fmaxf(ax * invd + b2v.x + r2v.x, 0.0f) * wlv.x;
        float vy = fmaxf(ay * invd + b2v.y + r2v.y, 0.0f) * wlv.y;
        float dot = vx + vy;
        #pragma unroll
        for (int s = 8; s; s >>= 1) dot += __shfl_xor_sync(0xFFFFFFFFu, dot, s);
        if (lane == 0) out[node] = dot + blv;
    }
}

// ---------------- launch ----------------
extern "C" void kernel_launch(void* const* d_in, const int* in_sizes, int n_in,
                              void* d_out, int out_size) {
    const float* x    = (const float*)d_in[0];
    const void*  ei   = d_in[1];
    const float* W1l  = (const float*)d_in[2];
    const float* b1   = (const float*)d_in[3];
    const float* W1r  = (const float*)d_in[4];
    const float* W2l  = (const float*)d_in[5];
    const float* b2   = (const float*)d_in[6];
    const float* W2r  = (const float*)d_in[7];
    const float* Wlin = (const float*)d_in[8];
    const float* blin = (const float*)d_in[9];
    float* out = (float*)d_out;

    static int attr_done = 0;
    if (!attr_done) {
        cudaFuncSetAttribute(fused1_k, cudaFuncAttributeMaxDynamicSharedMemorySize, 81920);
        attr_done = 1;
    }

    init_k<<<(N_NODES * 32 + 255) / 256, 256>>>(x, (const long long*)ei);
    hist_k<<<(E_EDGES / 4 + 255) / 256, 256>>>(ei);
    blocksum_k<<<SCAN_BLOCKS, 256>>>();
    scan_k2<<<SCAN_BLOCKS, 256>>>();
    fill_k<<<(E_EDGES / 4 + 255) / 256, 256>>>(ei);
    fused1_k<<<296, 256, 81920>>>(x, W1l, b1, W1r, W2l, W2r);
    fused2_k<<<1184, 256>>>(b2, Wlin, blin, out);
}

// round 9
// speedup vs baseline: 1.7731x; 1.0478x over previous
#include <cuda_runtime.h>
#include <cuda_bf16.h>
#include <cuda_fp16.h>

#define N_NODES 50000
#define E_EDGES 1600000
#define SCAN_BLOCKS 196   // 196 * 256 = 50176 >= 50000
#define N_TILES 12500     // 50000 / 4 exactly

// ---------------- scratch (device globals; no allocation allowed) ----------------
__device__ int     g_count[N_NODES];          // in-degree (int)
__device__ int     g_rowstart[N_NODES + 1];   // CSR row offsets (by dst)
__device__ int     g_cursor[N_NODES];         // fill cursors
__device__ int     g_srclist[E_EDGES];        // CSR: src ids bucketed by dst
__device__ int     g_blocksum[SCAN_BLOCKS];   // scan partials
__device__ __half2 g_xh[N_NODES * 32];        // x in half2 (channel pairs)
__device__ __half2 g_y2h[N_NODES * 16];       // h1 @ W2_l^T in half2 (channel pairs)
__device__ float   g_r2[N_NODES * 32];        // h1 @ W2_r^T (self term, layer 2)
__device__ int     g_is64;                    // edge_index dtype flag

// ---------------- packed f32x2 helpers ----------------
__device__ __forceinline__ unsigned long long pack2(float lo, float hi) {
    unsigned long long r;
    asm("mov.b64 %0, {%1, %2};" : "=l"(r) : "f"(lo), "f"(hi));
    return r;
}
__device__ __forceinline__ float2 unpack2(unsigned long long v) {
    float2 f;
    asm("mov.b64 {%0, %1}, %2;" : "=f"(f.x), "=f"(f.y) : "l"(v));
    return f;
}
__device__ __forceinline__ unsigned long long ffma2(unsigned long long a,
                                                    unsigned long long b,
                                                    unsigned long long c) {
    unsigned long long d;
    asm("fma.rn.f32x2 %0, %1, %2, %3;" : "=l"(d) : "l"(a), "l"(b), "l"(c));
    return d;
}
__device__ __forceinline__ unsigned long long fadd2(unsigned long long a,
                                                    unsigned long long b) {
    unsigned long long d;
    asm("add.rn.f32x2 %0, %1, %2;" : "=l"(d) : "l"(a), "l"(b));
    return d;
}

// half2-pair (uint2) -> 4 floats accumulate
__device__ __forceinline__ void acc4(uint2 u, float& a0, float& a1, float& a2, float& a3) {
    float2 p0 = __half22float2(*(__half2*)&u.x);
    float2 p1 = __half22float2(*(__half2*)&u.y);
    a0 += p0.x; a1 += p0.y; a2 += p1.x; a3 += p1.y;
}

// ---------------- init: zero counters + x->half2 conversion + dtype detection ----------------
__global__ void init_k(const float* __restrict__ x, const long long* __restrict__ ei) {
    int i = blockIdx.x * blockDim.x + threadIdx.x;
    if (i < N_NODES) g_count[i] = 0;
    if (i < N_NODES * 32) {
        float2 v = __ldg((const float2*)x + i);
        g_xh[i] = __float22half2_rn(v);
    }
    if (blockIdx.x == 0) {
        if (threadIdx.x == 0) g_is64 = 1;
        __syncthreads();
        if (threadIdx.x < 64) {
            long long v = ei[threadIdx.x];
            if (v < 0 || v >= N_NODES) atomicAnd(&g_is64, 0);
        }
    }
}

// ---------------- histogram of dst (4 edges / thread, vectorized loads) ----------------
__global__ void hist_k(const void* __restrict__ ei) {
    int e = (blockIdx.x * blockDim.x + threadIdx.x) * 4;
    if (e >= E_EDGES) return;
    int d0, d1, d2, d3;
    if (g_is64) {
        const longlong2* p = (const longlong2*)((const long long*)ei + E_EDGES + e);
        longlong2 a = __ldg(p), b = __ldg(p + 1);
        d0 = (int)a.x; d1 = (int)a.y; d2 = (int)b.x; d3 = (int)b.y;
    } else {
        int4 a = __ldg((const int4*)((const int*)ei + E_EDGES + e));
        d0 = a.x; d1 = a.y; d2 = a.z; d3 = a.w;
    }
    atomicAdd(&g_count[d0], 1);
    atomicAdd(&g_count[d1], 1);
    atomicAdd(&g_count[d2], 1);
    atomicAdd(&g_count[d3], 1);
}

// ---------------- scan stage 1: per-block sums ----------------
__global__ void blocksum_k() {
    __shared__ int sm[256];
    int t = threadIdx.x;
    int idx = blockIdx.x * 256 + t;
    sm[t] = (idx < N_NODES) ? g_count[idx] : 0;
    __syncthreads();
    #pragma unroll
    for (int s = 128; s; s >>= 1) {
        if (t < s) sm[t] += sm[t + s];
        __syncthreads();
    }
    if (t == 0) g_blocksum[blockIdx.x] = sm[0];
}

// ---------------- scan stage 2: redundant block-sum scan + local scan ----------------
__global__ void scan_k2() {
    __shared__ int bs[256];
    __shared__ int sm[256];
    int t = threadIdx.x;
    bs[t] = (t < SCAN_BLOCKS) ? g_blocksum[t] : 0;
    __syncthreads();
    #pragma unroll
    for (int st = 1; st < 256; st <<= 1) {
        int a = (t >= st) ? bs[t - st] : 0;
        __syncthreads();
        bs[t] += a;
        __syncthreads();
    }
    int blockoff = (blockIdx.x > 0) ? bs[blockIdx.x - 1] : 0;
    if (blockIdx.x == 0 && t == 0) g_rowstart[N_NODES] = bs[SCAN_BLOCKS - 1];

    int idx = blockIdx.x * 256 + t;
    int v = (idx < N_NODES) ? g_count[idx] : 0;
    sm[t] = v;
    __syncthreads();
    #pragma unroll
    for (int st = 1; st < 256; st <<= 1) {
        int a = (t >= st) ? sm[t - st] : 0;
        __syncthreads();
        sm[t] += a;
        __syncthreads();
    }
    if (idx < N_NODES) {
        int excl = sm[t] - v + blockoff;
        g_rowstart[idx] = excl;
        g_cursor[idx]   = excl;
    }
}

// ---------------- bucket fill (4 edges / thread, vectorized loads) ----------------
__global__ void fill_k(const void* __restrict__ ei) {
    int e = (blockIdx.x * blockDim.x + threadIdx.x) * 4;
    if (e >= E_EDGES) return;
    int s0, s1, s2, s3, d0, d1, d2, d3;
    if (g_is64) {
        const longlong2* ps = (const longlong2*)((const long long*)ei + e);
        const longlong2* pd = (const longlong2*)((const long long*)ei + E_EDGES + e);
        longlong2 a = __ldg(ps), b = __ldg(ps + 1);
        longlong2 c = __ldg(pd), d = __ldg(pd + 1);
        s0 = (int)a.x; s1 = (int)a.y; s2 = (int)b.x; s3 = (int)b.y;
        d0 = (int)c.x; d1 = (int)c.y; d2 = (int)d.x; d3 = (int)d.y;
    } else {
        int4 a = __ldg((const int4*)((const int*)ei + e));
        int4 c = __ldg((const int4*)((const int*)ei + E_EDGES + e));
        s0 = a.x; s1 = a.y; s2 = a.z; s3 = a.w;
        d0 = c.x; d1 = c.y; d2 = c.z; d3 = c.w;
    }
    g_srclist[atomicAdd(&g_cursor[d0], 1)] = s0;
    g_srclist[atomicAdd(&g_cursor[d1], 1)] = s1;
    g_srclist[atomicAdd(&g_cursor[d2], 1)] = s2;
    g_srclist[atomicAdd(&g_cursor[d3], 1)] = s3;
}

// ---------------- fused: gather x(half2, batched loads) + layer1 dense + layer2 pre ----------------
// One warp per 4-node tile. Gather: lanes 0-15 edge A, 16-31 edge B; lane owns
// channels 4*l16..4*l16+3 (uint2 = 2x half2). 16 edges per iteration with all
// srclist loads batched before all row loads (8 independent row LDGs in flight).
// Dense: lane owns channel pair (2*lane, 2*lane+1) packed f32x2.
// smem (dynamic 80KB): W4s 32KB | W2s 16KB | axs 32KB (8 warps)
__global__ void __launch_bounds__(256) fused1_k(
        const float* __restrict__ x,
        const float* __restrict__ W1l, const float* __restrict__ b1,
        const float* __restrict__ W1r,
        const float* __restrict__ W2l, const float* __restrict__ W2r) {
    extern __shared__ unsigned char sraw[];
    ulonglong2*         W4s = (ulonglong2*)sraw;                          // [k*32+o]
    unsigned long long* W2s = (unsigned long long*)(sraw + 32768);        // [k*32+o]
    ulonglong2*         axs = (ulonglong2*)(sraw + 49152);                // [warp][j][k]

    int tid = threadIdx.x;
    for (int i = tid; i < 2048; i += 256) {
        int k = i >> 5, o = i & 31;
        W4s[i] = make_ulonglong2(
            pack2(W1l[(2 * o) * 64 + k], W1l[(2 * o + 1) * 64 + k]),
            pack2(W1r[(2 * o) * 64 + k], W1r[(2 * o + 1) * 64 + k]));
        W2s[i] = pack2(W2l[o * 64 + k], W2r[o * 64 + k]);
    }
    __syncthreads();

    int w = tid >> 5, lane = tid & 31;
    int half = lane >> 4, l16 = lane & 15;
    unsigned long long b1v = pack2(__ldg(b1 + 2 * lane), __ldg(b1 + 2 * lane + 1));
    ulonglong2* axw = axs + w * 256;      // [j*64 + k]
    const uint2* xh2 = (const uint2*)g_xh;  // row = 16 uint2
    int nwarps = gridDim.x * 8;

    for (int t = blockIdx.x * 8 + w; t < N_TILES; t += nwarps) {
        int n0 = t * 4;
        __syncwarp();   // previous tile's axs reads complete

        // ---- gather 4 nodes' neighbor sums (16 edges / iter, batched loads) ----
        #pragma unroll
        for (int j = 0; j < 4; j++) {
            int node = n0 + j;
            int start = g_rowstart[node], end = g_rowstart[node + 1];
            float a0 = 0.0f, a1 = 0.0f, a2 = 0.0f, a3 = 0.0f;
            int i = start;
            for (; i + 16 <= end; i += 16) {
                int s[8];
                #pragma unroll
                for (int q = 0; q < 8; q++)
                    s[q] = __ldg(&g_srclist[i + 2 * q + half]);
                uint2 u[8];
                #pragma unroll
                for (int q = 0; q < 8; q++)
                    u[q] = __ldg(xh2 + (size_t)s[q] * 16 + l16);
                #pragma unroll
                for (int q = 0; q < 8; q++)
                    acc4(u[q], a0, a1, a2, a3);
            }
            if (i + 8 <= end) {
                int s[4];
                #pragma unroll
                for (int q = 0; q < 4; q++)
                    s[q] = __ldg(&g_srclist[i + 2 * q + half]);
                uint2 u[4];
                #pragma unroll
                for (int q = 0; q < 4; q++)
                    u[q] = __ldg(xh2 + (size_t)s[q] * 16 + l16);
                #pragma unroll
                for (int q = 0; q < 4; q++)
                    acc4(u[q], a0, a1, a2, a3);
                i += 8;
            }
            for (; i + 2 <= end; i += 2) {
                int s = __ldg(&g_srclist[i + half]);
                uint2 u = __ldg(xh2 + (size_t)s * 16 + l16);
                acc4(u, a0, a1, a2, a3);
            }
            if (i < end && half == 0) {
                int s = __ldg(&g_srclist[i]);
                uint2 u = __ldg(xh2 + (size_t)s * 16 + l16);
                acc4(u, a0, a1, a2, a3);
            }
            // combine the two half-warps
            a0 += __shfl_xor_sync(0xFFFFFFFFu, a0, 16);
            a1 += __shfl_xor_sync(0xFFFFFFFFu, a1, 16);
            a2 += __shfl_xor_sync(0xFFFFFFFFu, a2, 16);
            a3 += __shfl_xor_sync(0xFFFFFFFFu, a3, 16);

            float invd = 1.0f / fmaxf((float)(end - start), 1.0f);
            float4 xv = __ldg((const float4*)(x + (size_t)node * 64) + l16);  // self fp32
            if (half == 0) {
                axw[j * 64 + 4 * l16]     = make_ulonglong2(pack2(a0 * invd, a0 * invd),
                                                            pack2(xv.x, xv.x));
                axw[j * 64 + 4 * l16 + 1] = make_ulonglong2(pack2(a1 * invd, a1 * invd),
                                                            pack2(xv.y, xv.y));
            } else {
                axw[j * 64 + 4 * l16 + 2] = make_ulonglong2(pack2(a2 * invd, a2 * invd),
                                                            pack2(xv.z, xv.z));
                axw[j * 64 + 4 * l16 + 3] = make_ulonglong2(pack2(a3 * invd, a3 * invd),
                                                            pack2(xv.w, xv.w));
            }
        }
        __syncwarp();

        // ---- phase 1: dense GEMV, weight load shared by 4 nodes ----
        unsigned long long p0[4], p1[4];
        #pragma unroll
        for (int j = 0; j < 4; j++) { p0[j] = b1v; p1[j] = 0ull; }
        #pragma unroll 16
        for (int k = 0; k < 64; k++) {
            ulonglong2 wv = W4s[k * 32 + lane];
            #pragma unroll
            for (int j = 0; j < 4; j++) {
                ulonglong2 ax = axw[j * 64 + k];   // uniform broadcast
                p0[j] = ffma2(ax.x, wv.x, p0[j]);
                p1[j] = ffma2(ax.y, wv.y, p1[j]);
            }
        }
        float hL[4], hH[4];
        #pragma unroll
        for (int j = 0; j < 4; j++) {
            float2 h = unpack2(fadd2(p0[j], p1[j]));
            hL[j] = fmaxf(h.x, 0.0f);   // channel 2*lane
            hH[j] = fmaxf(h.y, 0.0f);   // channel 2*lane+1
        }

        // ---- phase 2: {y2, r2} per lane; W2 load shared by 4 nodes; h via shfl ----
        unsigned long long y0[4], y1[4];
        #pragma unroll
        for (int j = 0; j < 4; j++) { y0[j] = 0ull; y1[j] = 0ull; }
        #pragma unroll 8
        for (int k2 = 0; k2 < 32; k2++) {
            unsigned long long wA = W2s[(2 * k2) * 32 + lane];
            unsigned long long wB = W2s[(2 * k2 + 1) * 32 + lane];
            #pragma unroll
            for (int j = 0; j < 4; j++) {
                float ha = __shfl_sync(0xFFFFFFFFu, hL[j], k2);
                y0[j] = ffma2(pack2(ha, ha), wA, y0[j]);
                float hb = __shfl_sync(0xFFFFFFFFu, hH[j], k2);
                y1[j] = ffma2(pack2(hb, hb), wB, y1[j]);
            }
        }
        #pragma unroll
        for (int j = 0; j < 4; j++) {
            float2 yr = unpack2(fadd2(y0[j], y1[j]));   // {y2[lane], r2[lane]}
            int node = n0 + j;
            g_r2[(size_t)node * 32 + lane] = yr.y;
            float ynext = __shfl_down_sync(0xFFFFFFFFu, yr.x, 1);
            if ((lane & 1) == 0)
                g_y2h[(size_t)node * 16 + (lane >> 1)] = __floats2half2_rn(yr.x, ynext);
        }
    }
}

// ---------------- fused: gather y2(half2, batched loads) + final layer ----------------
// One warp per node; lanes 0-15 edge A, 16-31 edge B; lane owns channel pair
// (2*l16, 2*l16+1). 16 edges per iteration, loads batched before adds.
__global__ void __launch_bounds__(256) fused2_k(
        const float* __restrict__ b2, const float* __restrict__ Wlin,
        const float* __restrict__ blin, float* __restrict__ out) {
    int tid = threadIdx.x;
    int w = tid >> 5, lane = tid & 31;
    int half = lane >> 4, l16 = lane & 15;
    float2 b2v = __ldg((const float2*)b2 + l16);
    float2 wlv = __ldg((const float2*)Wlin + l16);
    float blv = __ldg(blin);
    int stride = gridDim.x * 8;

    for (int node = blockIdx.x * 8 + w; node < N_NODES; node += stride) {
        int start = g_rowstart[node], end = g_rowstart[node + 1];
        float ax = 0.0f, ay = 0.0f;
        int i = start;
        for (; i + 16 <= end; i += 16) {
            int s[8];
            #pragma unroll
            for (int q = 0; q < 8; q++)
                s[q] = __ldg(&g_srclist[i + 2 * q + half]);
            float2 v[8];
            #pragma unroll
            for (int q = 0; q < 8; q++)
                v[q] = __half22float2(g_y2h[(size_t)s[q] * 16 + l16]);
            #pragma unroll
            for (int q = 0; q < 8; q++) { ax += v[q].x; ay += v[q].y; }
        }
        if (i + 8 <= end) {
            int s[4];
            #pragma unroll
            for (int q = 0; q < 4; q++)
                s[q] = __ldg(&g_srclist[i + 2 * q + half]);
            float2 v[4];
            #pragma unroll
            for (int q = 0; q < 4; q++)
                v[q] = __half22float2(g_y2h[(size_t)s[q] * 16 + l16]);
            #pragma unroll
            for (int q = 0; q < 4; q++) { ax += v[q].x; ay += v[q].y; }
            i += 8;
        }
        for (; i + 2 <= end; i += 2) {
            int s = __ldg(&g_srclist[i + half]);
            float2 v = __half22float2(g_y2h[(size_t)s * 16 + l16]);
            ax += v.x; ay += v.y;
        }
        if (i < end && half == 0) {
            int s = __ldg(&g_srclist[i]);
            float2 v = __half22float2(g_y2h[(size_t)s * 16 + l16]);
            ax += v.x; ay += v.y;
        }
        ax += __shfl_xor_sync(0xFFFFFFFFu, ax, 16);
        ay += __shfl_xor_sync(0xFFFFFFFFu, ay, 16);

        float invd = 1.0f / fmaxf((float)(end - start), 1.0f);
        float2 r2v = __ldg((const float2*)(g_r2 + (size_t)node * 32) + l16);
        float vx = fmaxf(ax * invd + b2v.x + r2v.x, 0.0f) * wlv.x;
        float vy = fmaxf(ay * invd + b2v.y + r2v.y, 0.0f) * wlv.y;
        float dot = vx + vy;
        #pragma unroll
        for (int s = 8; s; s >>= 1) dot += __shfl_xor_sync(0xFFFFFFFFu, dot, s);
        if (lane == 0) out[node] = dot + blv;
    }
}

// ---------------- launch ----------------
extern "C" void kernel_launch(void* const* d_in, const int* in_sizes, int n_in,
                              void* d_out, int out_size) {
    const float* x    = (const float*)d_in[0];
    const void*  ei   = d_in[1];
    const float* W1l  = (const float*)d_in[2];
    const float* b1   = (const float*)d_in[3];
    const float* W1r  = (const float*)d_in[4];
    const float* W2l  = (const float*)d_in[5];
    const float* b2   = (const float*)d_in[6];
    const float* W2r  = (const float*)d_in[7];
    const float* Wlin = (const float*)d_in[8];
    const float* blin = (const float*)d_in[9];
    float* out = (float*)d_out;

    static int attr_done = 0;
    if (!attr_done) {
        cudaFuncSetAttribute(fused1_k, cudaFuncAttributeMaxDynamicSharedMemorySize, 81920);
        attr_done = 1;
    }

    init_k<<<(N_NODES * 32 + 255) / 256, 256>>>(x, (const long long*)ei);
    hist_k<<<(E_EDGES / 4 + 255) / 256, 256>>>(ei);
    blocksum_k<<<SCAN_BLOCKS, 256>>>();
    scan_k2<<<SCAN_BLOCKS, 256>>>();
    fill_k<<<(E_EDGES / 4 + 255) / 256, 256>>>(ei);
    fused1_k<<<296, 256, 81920>>>(x, W1l, b1, W1r, W2l, W2r);
    fused2_k<<<1184, 256>>>(b2, Wlin, blin, out);
}

// round 11
// speedup vs baseline: 1.9139x; 1.0794x over previous
#include <cuda_runtime.h>
#include <cuda_bf16.h>
#include <cuda_fp16.h>

#define N_NODES 50000
#define E_EDGES 1600000
#define SCAN_BLOCKS 196   // 196 * 256 = 50176 >= 50000
#define N_TILES 12500     // 50000 / 4 exactly

// ---------------- scratch (device globals; no allocation allowed) ----------------
__device__ int     g_count[N_NODES];          // in-degree (int)
__device__ int     g_rowstart[N_NODES + 1];   // CSR row offsets (by dst)
__device__ int     g_cursor[N_NODES];         // fill cursors
__device__ int     g_srclist[E_EDGES];        // CSR: src ids bucketed by dst
__device__ int     g_blocksum[SCAN_BLOCKS];   // scan partials
__device__ __half2 g_z1h[N_NODES * 32];       // x @ W1_l^T in half2 (channel pairs)
__device__ float   g_r1[N_NODES * 64];        // x @ W1_r^T + b1 (self term, layer 1)
__device__ __half2 g_y2h[N_NODES * 16];       // h1 @ W2_l^T in half2 (channel pairs)
__device__ float   g_r2[N_NODES * 32];        // h1 @ W2_r^T (self term, layer 2)
__device__ int     g_is64;                    // edge_index dtype flag

// ---------------- packed f32x2 helpers ----------------
__device__ __forceinline__ unsigned long long pack2(float lo, float hi) {
    unsigned long long r;
    asm("mov.b64 %0, {%1, %2};" : "=l"(r) : "f"(lo), "f"(hi));
    return r;
}
__device__ __forceinline__ float2 unpack2(unsigned long long v) {
    float2 f;
    asm("mov.b64 {%0, %1}, %2;" : "=f"(f.x), "=f"(f.y) : "l"(v));
    return f;
}
__device__ __forceinline__ unsigned long long ffma2(unsigned long long a,
                                                    unsigned long long b,
                                                    unsigned long long c) {
    unsigned long long d;
    asm("fma.rn.f32x2 %0, %1, %2, %3;" : "=l"(d) : "l"(a), "l"(b), "l"(c));
    return d;
}

// half2-pair (uint2) -> 4 floats accumulate
__device__ __forceinline__ void acc4(uint2 u, float& a0, float& a1, float& a2, float& a3) {
    float2 p0 = __half22float2(*(__half2*)&u.x);
    float2 p1 = __half22float2(*(__half2*)&u.y);
    a0 += p0.x; a1 += p0.y; a2 += p1.x; a3 += p1.y;
}

// ---------------- init: zero counters + dtype detection ----------------
__global__ void init_k(const long long* __restrict__ ei) {
    int i = blockIdx.x * blockDim.x + threadIdx.x;
    if (i < N_NODES) g_count[i] = 0;
    if (blockIdx.x == 0) {
        if (threadIdx.x == 0) g_is64 = 1;
        __syncthreads();
        if (threadIdx.x < 64) {
            long long v = ei[threadIdx.x];
            if (v < 0 || v >= N_NODES) atomicAnd(&g_is64, 0);
        }
    }
}

// ---------------- pre-projection layer 1: z1 = x@W1l^T (fp16), r1 = x@W1r^T + b1 ----------------
// One warp per 4-node tile; lane owns output channel pair (2*lane, 2*lane+1).
// smem 48KB static: Wl 16K | Wr 16K | xs 16K (splatted {x,x} per warp).
__global__ void __launch_bounds__(256) pre1_k(
        const float* __restrict__ x,
        const float* __restrict__ W1l, const float* __restrict__ b1,
        const float* __restrict__ W1r) {
    __shared__ unsigned long long Wl[64 * 32];
    __shared__ unsigned long long Wr[64 * 32];
    __shared__ unsigned long long xs[8][256];   // [warp][j*64+k] = {x,x}

    int tid = threadIdx.x;
    for (int i = tid; i < 2048; i += 256) {
        int k = i >> 5, o = i & 31;
        Wl[i] = pack2(W1l[(2 * o) * 64 + k], W1l[(2 * o + 1) * 64 + k]);
        Wr[i] = pack2(W1r[(2 * o) * 64 + k], W1r[(2 * o + 1) * 64 + k]);
    }
    __syncthreads();

    int w = tid >> 5, lane = tid & 31;
    unsigned long long b1v = pack2(__ldg(b1 + 2 * lane), __ldg(b1 + 2 * lane + 1));
    unsigned long long* xw = xs[w];
    int nwarps = gridDim.x * 8;

    for (int t = blockIdx.x * 8 + w; t < N_TILES; t += nwarps) {
        int n0 = t * 4;
        __syncwarp();
        #pragma unroll
        for (int j = 0; j < 4; j++) {
            float v0 = __ldg(x + (size_t)(n0 + j) * 64 + lane);
            float v1 = __ldg(x + (size_t)(n0 + j) * 64 + 32 + lane);
            xw[j * 64 + lane]      = pack2(v0, v0);
            xw[j * 64 + 32 + lane] = pack2(v1, v1);
        }
        __syncwarp();

        unsigned long long az[4], ar[4];
        #pragma unroll
        for (int j = 0; j < 4; j++) { az[j] = 0ull; ar[j] = b1v; }
        #pragma unroll 16
        for (int k = 0; k < 64; k++) {
            unsigned long long wl = Wl[k * 32 + lane];
            unsigned long long wr = Wr[k * 32 + lane];
            #pragma unroll
            for (int j = 0; j < 4; j++) {
                unsigned long long xv = xw[j * 64 + k];   // uniform broadcast
                az[j] = ffma2(xv, wl, az[j]);
                ar[j] = ffma2(xv, wr, ar[j]);
            }
        }
        #pragma unroll
        for (int j = 0; j < 4; j++) {
            int node = n0 + j;
            float2 z = unpack2(az[j]);
            float2 r = unpack2(ar[j]);
            g_z1h[(size_t)node * 32 + lane] = __floats2half2_rn(z.x, z.y);
            ((float2*)g_r1)[(size_t)node * 32 + lane] = r;
        }
    }
}

// ---------------- histogram of dst (4 edges / thread, vectorized loads) ----------------
__global__ void hist_k(const void* __restrict__ ei) {
    int e = (blockIdx.x * blockDim.x + threadIdx.x) * 4;
    if (e >= E_EDGES) return;
    int d0, d1, d2, d3;
    if (g_is64) {
        const longlong2* p = (const longlong2*)((const long long*)ei + E_EDGES + e);
        longlong2 a = __ldg(p), b = __ldg(p + 1);
        d0 = (int)a.x; d1 = (int)a.y; d2 = (int)b.x; d3 = (int)b.y;
    } else {
        int4 a = __ldg((const int4*)((const int*)ei + E_EDGES + e));
        d0 = a.x; d1 = a.y; d2 = a.z; d3 = a.w;
    }
    atomicAdd(&g_count[d0], 1);
    atomicAdd(&g_count[d1], 1);
    atomicAdd(&g_count[d2], 1);
    atomicAdd(&g_count[d3], 1);
}

// ---------------- scan stage 1: per-block sums ----------------
__global__ void blocksum_k() {
    __shared__ int sm[256];
    int t = threadIdx.x;
    int idx = blockIdx.x * 256 + t;
    sm[t] = (idx < N_NODES) ? g_count[idx] : 0;
    __syncthreads();
    #pragma unroll
    for (int s = 128; s; s >>= 1) {
        if (t < s) sm[t] += sm[t + s];
        __syncthreads();
    }
    if (t == 0) g_blocksum[blockIdx.x] = sm[0];
}

// ---------------- scan stage 2: redundant block-sum scan + local scan ----------------
__global__ void scan_k2() {
    __shared__ int bs[256];
    __shared__ int sm[256];
    int t = threadIdx.x;
    bs[t] = (t < SCAN_BLOCKS) ? g_blocksum[t] : 0;
    __syncthreads();
    #pragma unroll
    for (int st = 1; st < 256; st <<= 1) {
        int a = (t >= st) ? bs[t - st] : 0;
        __syncthreads();
        bs[t] += a;
        __syncthreads();
    }
    int blockoff = (blockIdx.x > 0) ? bs[blockIdx.x - 1] : 0;
    if (blockIdx.x == 0 && t == 0) g_rowstart[N_NODES] = bs[SCAN_BLOCKS - 1];

    int idx = blockIdx.x * 256 + t;
    int v = (idx < N_NODES) ? g_count[idx] : 0;
    sm[t] = v;
    __syncthreads();
    #pragma unroll
    for (int st = 1; st < 256; st <<= 1) {
        int a = (t >= st) ? sm[t - st] : 0;
        __syncthreads();
        sm[t] += a;
        __syncthreads();
    }
    if (idx < N_NODES) {
        int excl = sm[t] - v + blockoff;
        g_rowstart[idx] = excl;
        g_cursor[idx]   = excl;
    }
}

// ---------------- bucket fill (4 edges / thread, vectorized loads) ----------------
__global__ void fill_k(const void* __restrict__ ei) {
    int e = (blockIdx.x * blockDim.x + threadIdx.x) * 4;
    if (e >= E_EDGES) return;
    int s0, s1, s2, s3, d0, d1, d2, d3;
    if (g_is64) {
        const longlong2* ps = (const longlong2*)((const long long*)ei + e);
        const longlong2* pd = (const longlong2*)((const long long*)ei + E_EDGES + e);
        longlong2 a = __ldg(ps), b = __ldg(ps + 1);
        longlong2 c = __ldg(pd), d = __ldg(pd + 1);
        s0 = (int)a.x; s1 = (int)a.y; s2 = (int)b.x; s3 = (int)b.y;
        d0 = (int)c.x; d1 = (int)c.y; d2 = (int)d.x; d3 = (int)d.y;
    } else {
        int4 a = __ldg((const int4*)((const int*)ei + e));
        int4 c = __ldg((const int4*)((const int*)ei + E_EDGES + e));
        s0 = a.x; s1 = a.y; s2 = a.z; s3 = a.w;
        d0 = c.x; d1 = c.y; d2 = c.z; d3 = c.w;
    }
    g_srclist[atomicAdd(&g_cursor[d0], 1)] = s0;
    g_srclist[atomicAdd(&g_cursor[d1], 1)] = s1;
    g_srclist[atomicAdd(&g_cursor[d2], 1)] = s2;
    g_srclist[atomicAdd(&g_cursor[d3], 1)] = s3;
}

// ---------------- fused: gather z1(half2) + relu(mean + r1) + layer2 fold ----------------
// One warp per 4-node tile. Gather: lanes 0-15 edge A, 16-31 edge B; lane owns
// channels 4*l16..4*l16+3 (uint2). h1 is elementwise (no GEMV!). Layer-2 fold
// (y2 = h1@W2l^T, r2 = h1@W2r^T) uses splatted h in smem + shared W2 loads.
// smem 32KB static: W2s 16K | hs 16K.
__global__ void __launch_bounds__(256) fused1_k(
        const float* __restrict__ W2l, const float* __restrict__ W2r) {
    __shared__ unsigned long long W2s[64 * 32];   // [k*32+o] = {W2l[o][k], W2r[o][k]}
    __shared__ unsigned long long hs[8][256];     // [warp][j*64+k] = {h,h}

    int tid = threadIdx.x;
    for (int i = tid; i < 2048; i += 256) {
        int k = i >> 5, o = i & 31;
        W2s[i] = pack2(W2l[o * 64 + k], W2r[o * 64 + k]);
    }
    __syncthreads();

    int w = tid >> 5, lane = tid & 31;
    int half = lane >> 4, l16 = lane & 15;
    unsigned long long* hw = hs[w];
    const uint2* zh2 = (const uint2*)g_z1h;   // row = 16 uint2
    int nwarps = gridDim.x * 8;

    for (int t = blockIdx.x * 8 + w; t < N_TILES; t += nwarps) {
        int n0 = t * 4;
        __syncwarp();   // previous tile's hs reads complete

        // ---- gather 4 nodes' neighbor means + elementwise h1 ----
        #pragma unroll
        for (int j = 0; j < 4; j++) {
            int node = n0 + j;
            int start = g_rowstart[node], end = g_rowstart[node + 1];
            float a0 = 0.0f, a1 = 0.0f, a2 = 0.0f, a3 = 0.0f;
            int i = start;
            for (; i + 16 <= end; i += 16) {
                int s[8];
                #pragma unroll
                for (int q = 0; q < 8; q++)
                    s[q] = __ldg(&g_srclist[i + 2 * q + half]);
                uint2 u[8];
                #pragma unroll
                for (int q = 0; q < 8; q++)
                    u[q] = __ldg(zh2 + (size_t)s[q] * 16 + l16);
                #pragma unroll
                for (int q = 0; q < 8; q++)
                    acc4(u[q], a0, a1, a2, a3);
            }
            if (i + 8 <= end) {
                int s[4];
                #pragma unroll
                for (int q = 0; q < 4; q++)
                    s[q] = __ldg(&g_srclist[i + 2 * q + half]);
                uint2 u[4];
                #pragma unroll
                for (int q = 0; q < 4; q++)
                    u[q] = __ldg(zh2 + (size_t)s[q] * 16 + l16);
                #pragma unroll
                for (int q = 0; q < 4; q++)
                    acc4(u[q], a0, a1, a2, a3);
                i += 8;
            }
            for (; i + 2 <= end; i += 2) {
                int s = __ldg(&g_srclist[i + half]);
                uint2 u = __ldg(zh2 + (size_t)s * 16 + l16);
                acc4(u, a0, a1, a2, a3);
            }
            if (i < end && half == 0) {
                int s = __ldg(&g_srclist[i]);
                uint2 u = __ldg(zh2 + (size_t)s * 16 + l16);
                acc4(u, a0, a1, a2, a3);
            }
            // combine the two half-warps
            a0 += __shfl_xor_sync(0xFFFFFFFFu, a0, 16);
            a1 += __shfl_xor_sync(0xFFFFFFFFu, a1, 16);
            a2 += __shfl_xor_sync(0xFFFFFFFFu, a2, 16);
            a3 += __shfl_xor_sync(0xFFFFFFFFu, a3, 16);

            float invd = 1.0f / fmaxf((float)(end - start), 1.0f);
            float4 rv = __ldg((const float4*)(g_r1 + (size_t)node * 64) + l16);
            float h0 = fmaxf(a0 * invd + rv.x, 0.0f);
            float h1 = fmaxf(a1 * invd + rv.y, 0.0f);
            float h2 = fmaxf(a2 * invd + rv.z, 0.0f);
            float h3 = fmaxf(a3 * invd + rv.w, 0.0f);
            if (half == 0) {
                hw[j * 64 + 4 * l16]     = pack2(h0, h0);
                hw[j * 64 + 4 * l16 + 1] = pack2(h1, h1);
            } else {
                hw[j * 64 + 4 * l16 + 2] = pack2(h2, h2);
                hw[j * 64 + 4 * l16 + 3] = pack2(h3, h3);
            }
        }
        __syncwarp();

        // ---- layer-2 fold: {y2, r2} per lane; W2 load shared by 4 nodes ----
        unsigned long long y[4];
        #pragma unroll
        for (int j = 0; j < 4; j++) y[j] = 0ull;
        #pragma unroll 16
        for (int k = 0; k < 64; k++) {
            unsigned long long wv = W2s[k * 32 + lane];
            #pragma unroll
            for (int j = 0; j < 4; j++) {
                unsigned long long hv = hw[j * 64 + k];   // uniform broadcast
                y[j] = ffma2(hv, wv, y[j]);
            }
        }
        #pragma unroll
        for (int j = 0; j < 4; j++) {
            float2 yr = unpack2(y[j]);   // {y2[lane], r2[lane]}
            int node = n0 + j;
            g_r2[(size_t)node * 32 + lane] = yr.y;
            float ynext = __shfl_down_sync(0xFFFFFFFFu, yr.x, 1);
            if ((lane & 1) == 0)
                g_y2h[(size_t)node * 16 + (lane >> 1)] = __floats2half2_rn(yr.x, ynext);
        }
    }
}

// ---------------- fused: gather y2(half2, batched loads) + final layer ----------------
__global__ void __launch_bounds__(256) fused2_k(
        const float* __restrict__ b2, const float* __restrict__ Wlin,
        const float* __restrict__ blin, float* __restrict__ out) {
    int tid = threadIdx.x;
    int w = tid >> 5, lane = tid & 31;
    int half = lane >> 4, l16 = lane & 15;
    float2 b2v = __ldg((const float2*)b2 + l16);
    float2 wlv = __ldg((const float2*)Wlin + l16);
    float blv = __ldg(blin);
    int stride = gridDim.x * 8;

    for (int node = blockIdx.x * 8 + w; node < N_NODES; node += stride) {
        int start = g_rowstart[node], end = g_rowstart[node + 1];
        float ax = 0.0f, ay = 0.0f;
        int i = start;
        for (; i + 16 <= end; i += 16) {
            int s[8];
            #pragma unroll
            for (int q = 0; q < 8; q++)
                s[q] = __ldg(&g_srclist[i + 2 * q + half]);
            float2 v[8];
            #pragma unroll
            for (int q = 0; q < 8; q++)
                v[q] = __half22float2(g_y2h[(size_t)s[q] * 16 + l16]);
            #pragma unroll
            for (int q = 0; q < 8; q++) { ax += v[q].x; ay += v[q].y; }
        }
        if (i + 8 <= end) {
            int s[4];
            #pragma unroll
            for (int q = 0; q < 4; q++)
                s[q] = __ldg(&g_srclist[i + 2 * q + half]);
            float2 v[4];
            #pragma unroll
            for (int q = 0; q < 4; q++)
                v[q] = __half22float2(g_y2h[(size_t)s[q] * 16 + l16]);
            #pragma unroll
            for (int q = 0; q < 4; q++) { ax += v[q].x; ay += v[q].y; }
            i += 8;
        }
        for (; i + 2 <= end; i += 2) {
            int s = __ldg(&g_srclist[i + half]);
            float2 v = __half22float2(g_y2h[(size_t)s * 16 + l16]);
            ax += v.x; ay += v.y;
        }
        if (i < end && half == 0) {
            int s = __ldg(&g_srclist[i]);
            float2 v = __half22float2(g_y2h[(size_t)s * 16 + l16]);
            ax += v.x; ay += v.y;
        }
        ax += __shfl_xor_sync(0xFFFFFFFFu, ax, 16);
        ay += __shfl_xor_sync(0xFFFFFFFFu, ay, 16);

        float invd = 1.0f / fmaxf((float)(end - start), 1.0f);
        float2 r2v = __ldg((const float2*)(g_r2 + (size_t)node * 32) + l16);
        float vx = fmaxf(ax * invd + b2v.x + r2v.x, 0.0f) * wlv.x;
        float vy = fmaxf(ay * invd + b2v.y + r2v.y, 0.0f) * wlv.y;
        float dot = vx + vy;
        #pragma unroll
        for (int s = 8; s; s >>= 1) dot += __shfl_xor_sync(0xFFFFFFFFu, dot, s);
        if (lane == 0) out[node] = dot + blv;
    }
}

// ---------------- launch ----------------
extern "C" void kernel_launch(void* const* d_in, const int* in_sizes, int n_in,
                              void* d_out, int out_size) {
    const float* x    = (const float*)d_in[0];
    const void*  ei   = d_in[1];
    const float* W1l  = (const float*)d_in[2];
    const float* b1   = (const float*)d_in[3];
    const float* W1r  = (const float*)d_in[4];
    const float* W2l  = (const float*)d_in[5];
    const float* b2   = (const float*)d_in[6];
    const float* W2r  = (const float*)d_in[7];
    const float* Wlin = (const float*)d_in[8];
    const float* blin = (const float*)d_in[9];
    float* out = (float*)d_out;

    init_k<<<(N_NODES + 255) / 256, 256>>>((const long long*)ei);
    pre1_k<<<592, 256>>>(x, W1l, b1, W1r);
    hist_k<<<(E_EDGES / 4 + 255) / 256, 256>>>(ei);
    blocksum_k<<<SCAN_BLOCKS, 256>>>();
    scan_k2<<<SCAN_BLOCKS, 256>>>();
    fill_k<<<(E_EDGES / 4 + 255) / 256, 256>>>(ei);
    fused1_k<<<1184, 256>>>(W2l, W2r);
    fused2_k<<<1184, 256>>>(b2, Wlin, blin, out);
}

// round 13
// speedup vs baseline: 1.9730x; 1.0308x over previous
#include <cuda_runtime.h>
#include <cuda_bf16.h>
#include <cuda_fp16.h>

#define N_NODES 50000
#define E_EDGES 1600000
#define SCAN_BLOCKS 196   // 196 * 256 = 50176 >= 50000
#define N_TILES 12500     // 50000 / 4 exactly

// ---------------- scratch (device globals; no allocation allowed) ----------------
__device__ int     g_count[N_NODES];          // in-degree (int)
__device__ int     g_rowstart[N_NODES + 1];   // CSR row offsets (by dst)
__device__ int     g_cursor[N_NODES];         // fill cursors
__device__ int     g_srclist[E_EDGES];        // CSR: src ids bucketed by dst
__device__ int     g_blocksum[SCAN_BLOCKS];   // scan partials
__device__ __half2 g_z1h[N_NODES * 32];       // x @ W1_l^T in half2 (channel pairs)
__device__ float   g_r1[N_NODES * 64];        // x @ W1_r^T + b1 (self term, layer 1)
__device__ __half2 g_y2h[N_NODES * 16];       // h1 @ W2_l^T in half2 (channel pairs)
__device__ float   g_r2[N_NODES * 32];        // h1 @ W2_r^T (self term, layer 2)
__device__ int     g_is64;                    // edge_index dtype flag

// ---------------- packed f32x2 helpers ----------------
__device__ __forceinline__ unsigned long long pack2(float lo, float hi) {
    unsigned long long r;
    asm("mov.b64 %0, {%1, %2};" : "=l"(r) : "f"(lo), "f"(hi));
    return r;
}
__device__ __forceinline__ float2 unpack2(unsigned long long v) {
    float2 f;
    asm("mov.b64 {%0, %1}, %2;" : "=f"(f.x), "=f"(f.y) : "l"(v));
    return f;
}
__device__ __forceinline__ unsigned long long ffma2(unsigned long long a,
                                                    unsigned long long b,
                                                    unsigned long long c) {
    unsigned long long d;
    asm("fma.rn.f32x2 %0, %1, %2, %3;" : "=l"(d) : "l"(a), "l"(b), "l"(c));
    return d;
}

// uint4 (4x half2 = 8 channels) -> accumulate into 8 floats
__device__ __forceinline__ void acc8(uint4 u, float* a) {
    float2 p0 = __half22float2(*(__half2*)&u.x);
    float2 p1 = __half22float2(*(__half2*)&u.y);
    float2 p2 = __half22float2(*(__half2*)&u.z);
    float2 p3 = __half22float2(*(__half2*)&u.w);
    a[0] += p0.x; a[1] += p0.y; a[2] += p1.x; a[3] += p1.y;
    a[4] += p2.x; a[5] += p2.y; a[6] += p3.x; a[7] += p3.y;
}

// ---------------- init: zero counters + dtype detection ----------------
__global__ void init_k(const long long* __restrict__ ei) {
    int i = blockIdx.x * blockDim.x + threadIdx.x;
    if (i < N_NODES) g_count[i] = 0;
    if (blockIdx.x == 0) {
        if (threadIdx.x == 0) g_is64 = 1;
        __syncthreads();
        if (threadIdx.x < 64) {
            long long v = ei[threadIdx.x];
            if (v < 0 || v >= N_NODES) atomicAnd(&g_is64, 0);
        }
    }
}

// ---------------- pre-projection layer 1: z1 = x@W1l^T (fp16), r1 = x@W1r^T + b1 ----------------
__global__ void __launch_bounds__(256) pre1_k(
        const float* __restrict__ x,
        const float* __restrict__ W1l, const float* __restrict__ b1,
        const float* __restrict__ W1r) {
    __shared__ unsigned long long Wl[64 * 32];
    __shared__ unsigned long long Wr[64 * 32];
    __shared__ unsigned long long xs[8][256];   // [warp][j*64+k] = {x,x}

    int tid = threadIdx.x;
    for (int i = tid; i < 2048; i += 256) {
        int k = i >> 5, o = i & 31;
        Wl[i] = pack2(W1l[(2 * o) * 64 + k], W1l[(2 * o + 1) * 64 + k]);
        Wr[i] = pack2(W1r[(2 * o) * 64 + k], W1r[(2 * o + 1) * 64 + k]);
    }
    __syncthreads();

    int w = tid >> 5, lane = tid & 31;
    unsigned long long b1v = pack2(__ldg(b1 + 2 * lane), __ldg(b1 + 2 * lane + 1));
    unsigned long long* xw = xs[w];
    int nwarps = gridDim.x * 8;

    for (int t = blockIdx.x * 8 + w; t < N_TILES; t += nwarps) {
        int n0 = t * 4;
        __syncwarp();
        #pragma unroll
        for (int j = 0; j < 4; j++) {
            float v0 = __ldg(x + (size_t)(n0 + j) * 64 + lane);
            float v1 = __ldg(x + (size_t)(n0 + j) * 64 + 32 + lane);
            xw[j * 64 + lane]      = pack2(v0, v0);
            xw[j * 64 + 32 + lane] = pack2(v1, v1);
        }
        __syncwarp();

        unsigned long long az[4], ar[4];
        #pragma unroll
        for (int j = 0; j < 4; j++) { az[j] = 0ull; ar[j] = b1v; }
        #pragma unroll 16
        for (int k = 0; k < 64; k++) {
            unsigned long long wl = Wl[k * 32 + lane];
            unsigned long long wr = Wr[k * 32 + lane];
            #pragma unroll
            for (int j = 0; j < 4; j++) {
                unsigned long long xv = xw[j * 64 + k];   // uniform broadcast
                az[j] = ffma2(xv, wl, az[j]);
                ar[j] = ffma2(xv, wr, ar[j]);
            }
        }
        #pragma unroll
        for (int j = 0; j < 4; j++) {
            int node = n0 + j;
            float2 z = unpack2(az[j]);
            float2 r = unpack2(ar[j]);
            g_z1h[(size_t)node * 32 + lane] = __floats2half2_rn(z.x, z.y);
            ((float2*)g_r1)[(size_t)node * 32 + lane] = r;
        }
    }
}

// ---------------- histogram of dst (4 edges / thread, vectorized loads) ----------------
__global__ void hist_k(const void* __restrict__ ei) {
    int e = (blockIdx.x * blockDim.x + threadIdx.x) * 4;
    if (e >= E_EDGES) return;
    int d0, d1, d2, d3;
    if (g_is64) {
        const longlong2* p = (const longlong2*)((const long long*)ei + E_EDGES + e);
        longlong2 a = __ldg(p), b = __ldg(p + 1);
        d0 = (int)a.x; d1 = (int)a.y; d2 = (int)b.x; d3 = (int)b.y;
    } else {
        int4 a = __ldg((const int4*)((const int*)ei + E_EDGES + e));
        d0 = a.x; d1 = a.y; d2 = a.z; d3 = a.w;
    }
    atomicAdd(&g_count[d0], 1);
    atomicAdd(&g_count[d1], 1);
    atomicAdd(&g_count[d2], 1);
    atomicAdd(&g_count[d3], 1);
}

// ---------------- scan stage 1: per-block sums ----------------
__global__ void blocksum_k() {
    __shared__ int sm[256];
    int t = threadIdx.x;
    int idx = blockIdx.x * 256 + t;
    sm[t] = (idx < N_NODES) ? g_count[idx] : 0;
    __syncthreads();
    #pragma unroll
    for (int s = 128; s; s >>= 1) {
        if (t < s) sm[t] += sm[t + s];
        __syncthreads();
    }
    if (t == 0) g_blocksum[blockIdx.x] = sm[0];
}

// ---------------- scan stage 2: redundant block-sum scan + local scan ----------------
__global__ void scan_k2() {
    __shared__ int bs[256];
    __shared__ int sm[256];
    int t = threadIdx.x;
    bs[t] = (t < SCAN_BLOCKS) ? g_blocksum[t] : 0;
    __syncthreads();
    #pragma unroll
    for (int st = 1; st < 256; st <<= 1) {
        int a = (t >= st) ? bs[t - st] : 0;
        __syncthreads();
        bs[t] += a;
        __syncthreads();
    }
    int blockoff = (blockIdx.x > 0) ? bs[blockIdx.x - 1] : 0;
    if (blockIdx.x == 0 && t == 0) g_rowstart[N_NODES] = bs[SCAN_BLOCKS - 1];

    int idx = blockIdx.x * 256 + t;
    int v = (idx < N_NODES) ? g_count[idx] : 0;
    sm[t] = v;
    __syncthreads();
    #pragma unroll
    for (int st = 1; st < 256; st <<= 1) {
        int a = (t >= st) ? sm[t - st] : 0;
        __syncthreads();
        sm[t] += a;
        __syncthreads();
    }
    if (idx < N_NODES) {
        int excl = sm[t] - v + blockoff;
        g_rowstart[idx] = excl;
        g_cursor[idx]   = excl;
    }
}

// ---------------- bucket fill (4 edges / thread, vectorized loads) ----------------
__global__ void fill_k(const void* __restrict__ ei) {
    int e = (blockIdx.x * blockDim.x + threadIdx.x) * 4;
    if (e >= E_EDGES) return;
    int s0, s1, s2, s3, d0, d1, d2, d3;
    if (g_is64) {
        const longlong2* ps = (const longlong2*)((const long long*)ei + e);
        const longlong2* pd = (const longlong2*)((const long long*)ei + E_EDGES + e);
        longlong2 a = __ldg(ps), b = __ldg(ps + 1);
        longlong2 c = __ldg(pd), d = __ldg(pd + 1);
        s0 = (int)a.x; s1 = (int)a.y; s2 = (int)b.x; s3 = (int)b.y;
        d0 = (int)c.x; d1 = (int)c.y; d2 = (int)d.x; d3 = (int)d.y;
    } else {
        int4 a = __ldg((const int4*)((const int*)ei + e));
        int4 c = __ldg((const int4*)((const int*)ei + E_EDGES + e));
        s0 = a.x; s1 = a.y; s2 = a.z; s3 = a.w;
        d0 = c.x; d1 = c.y; d2 = c.z; d3 = c.w;
    }
    g_srclist[atomicAdd(&g_cursor[d0], 1)] = s0;
    g_srclist[atomicAdd(&g_cursor[d1], 1)] = s1;
    g_srclist[atomicAdd(&g_cursor[d2], 1)] = s2;
    g_srclist[atomicAdd(&g_cursor[d3], 1)] = s3;
}

// ---------------- fused: gather z1 (4 edges/step, uint4) + relu(mean+r1) + layer2 fold ----------------
// qid = lane>>3 selects edge within step; l8 = lane&7 owns channels 8*l8..8*l8+7.
// smem 32KB static: W2s 16K | hs 16K.
__global__ void __launch_bounds__(256) fused1_k(
        const float* __restrict__ W2l, const float* __restrict__ W2r) {
    __shared__ unsigned long long W2s[64 * 32];   // [k*32+o] = {W2l[o][k], W2r[o][k]}
    __shared__ unsigned long long hs[8][256];     // [warp][j*64+k] = {h,h}

    int tid = threadIdx.x;
    for (int i = tid; i < 2048; i += 256) {
        int k = i >> 5, o = i & 31;
        W2s[i] = pack2(W2l[o * 64 + k], W2r[o * 64 + k]);
    }
    __syncthreads();

    int w = tid >> 5, lane = tid & 31;
    int qid = lane >> 3, l8 = lane & 7;
    unsigned long long* hw = hs[w];
    const uint4* zrow = (const uint4*)g_z1h;   // row = 8 uint4
    int nwarps = gridDim.x * 8;

    for (int t = blockIdx.x * 8 + w; t < N_TILES; t += nwarps) {
        int n0 = t * 4;
        __syncwarp();   // previous tile's hs reads complete

        // ---- gather 4 nodes' neighbor means + elementwise h1 ----
        #pragma unroll
        for (int j = 0; j < 4; j++) {
            int node = n0 + j;
            int start = g_rowstart[node], end = g_rowstart[node + 1];
            float a[8] = {0, 0, 0, 0, 0, 0, 0, 0};
            int i = start;
            for (; i + 32 <= end; i += 32) {
                int s[8];
                #pragma unroll
                for (int q = 0; q < 8; q++)
                    s[q] = __ldg(&g_srclist[i + 4 * q + qid]);
                uint4 u[8];
                #pragma unroll
                for (int q = 0; q < 8; q++)
                    u[q] = __ldg(zrow + (size_t)s[q] * 8 + l8);
                #pragma unroll
                for (int q = 0; q < 8; q++) acc8(u[q], a);
            }
            if (i + 16 <= end) {
                int s[4];
                #pragma unroll
                for (int q = 0; q < 4; q++)
                    s[q] = __ldg(&g_srclist[i + 4 * q + qid]);
                uint4 u[4];
                #pragma unroll
                for (int q = 0; q < 4; q++)
                    u[q] = __ldg(zrow + (size_t)s[q] * 8 + l8);
                #pragma unroll
                for (int q = 0; q < 4; q++) acc8(u[q], a);
                i += 16;
            }
            if (i + 8 <= end) {
                int s0 = __ldg(&g_srclist[i + qid]);
                int s1 = __ldg(&g_srclist[i + 4 + qid]);
                uint4 u0 = __ldg(zrow + (size_t)s0 * 8 + l8);
                uint4 u1 = __ldg(zrow + (size_t)s1 * 8 + l8);
                acc8(u0, a); acc8(u1, a);
                i += 8;
            }
            if (i + 4 <= end) {
                int s0 = __ldg(&g_srclist[i + qid]);
                uint4 u0 = __ldg(zrow + (size_t)s0 * 8 + l8);
                acc8(u0, a);
                i += 4;
            }
            int rem = end - i;
            if (qid < rem) {
                int s0 = __ldg(&g_srclist[i + qid]);
                uint4 u0 = __ldg(zrow + (size_t)s0 * 8 + l8);
                acc8(u0, a);
            }
            // combine the 4 edge-groups (lane bits 3,4)
            #pragma unroll
            for (int c = 0; c < 8; c++) {
                a[c] += __shfl_xor_sync(0xFFFFFFFFu, a[c], 8);
                a[c] += __shfl_xor_sync(0xFFFFFFFFu, a[c], 16);
            }
            // this lane finalizes channels 8*l8 + 2*qid, +1
            float s0 = a[0], s1 = a[1];
            if (qid == 1) { s0 = a[2]; s1 = a[3]; }
            else if (qid == 2) { s0 = a[4]; s1 = a[5]; }
            else if (qid == 3) { s0 = a[6]; s1 = a[7]; }
            float invd = 1.0f / fmaxf((float)(end - start), 1.0f);
            float2 rv = __ldg(((const float2*)(g_r1 + (size_t)node * 64)) + 4 * l8 + qid);
            float h0 = fmaxf(s0 * invd + rv.x, 0.0f);
            float h1 = fmaxf(s1 * invd + rv.y, 0.0f);
            ((ulonglong2*)hw)[j * 32 + 4 * l8 + qid] =
                make_ulonglong2(pack2(h0, h0), pack2(h1, h1));
        }
        __syncwarp();

        // ---- layer-2 fold: {y2, r2} per lane; W2 load shared by 4 nodes ----
        unsigned long long y[4];
        #pragma unroll
        for (int j = 0; j < 4; j++) y[j] = 0ull;
        #pragma unroll 16
        for (int k = 0; k < 64; k++) {
            unsigned long long wv = W2s[k * 32 + lane];
            #pragma unroll
            for (int j = 0; j < 4; j++) {
                unsigned long long hv = hw[j * 64 + k];   // uniform broadcast
                y[j] = ffma2(hv, wv, y[j]);
            }
        }
        #pragma unroll
        for (int j = 0; j < 4; j++) {
            float2 yr = unpack2(y[j]);   // {y2[lane], r2[lane]}
            int node = n0 + j;
            g_r2[(size_t)node * 32 + lane] = yr.y;
            float ynext = __shfl_down_sync(0xFFFFFFFFu, yr.x, 1);
            if ((lane & 1) == 0)
                g_y2h[(size_t)node * 16 + (lane >> 1)] = __floats2half2_rn(yr.x, ynext);
        }
    }
}

// ---------------- fused: gather y2 (8 edges/step, uint4) + final layer ----------------
// qid = lane>>2 selects edge within step; l4 = lane&3 owns channels 8*l4..8*l4+7.
__global__ void __launch_bounds__(256) fused2_k(
        const float* __restrict__ b2, const float* __restrict__ Wlin,
        const float* __restrict__ blin, float* __restrict__ out) {
    int tid = threadIdx.x;
    int w = tid >> 5, lane = tid & 31;
    int qid = lane >> 2, l4 = lane & 3;
    float4 b2a = __ldg((const float4*)b2 + 2 * l4);
    float4 b2b = __ldg((const float4*)b2 + 2 * l4 + 1);
    float4 wla = __ldg((const float4*)Wlin + 2 * l4);
    float4 wlb = __ldg((const float4*)Wlin + 2 * l4 + 1);
    float blv = __ldg(blin);
    const uint4* yrow = (const uint4*)g_y2h;   // row = 4 uint4
    int stride = gridDim.x * 8;

    for (int node = blockIdx.x * 8 + w; node < N_NODES; node += stride) {
        int start = g_rowstart[node], end = g_rowstart[node + 1];
        float a[8] = {0, 0, 0, 0, 0, 0, 0, 0};
        int i = start;
        for (; i + 32 <= end; i += 32) {
            int s[4];
            #pragma unroll
            for (int q = 0; q < 4; q++)
                s[q] = __ldg(&g_srclist[i + 8 * q + qid]);
            uint4 u[4];
            #pragma unroll
            for (int q = 0; q < 4; q++)
                u[q] = __ldg(yrow + (size_t)s[q] * 4 + l4);
            #pragma unroll
            for (int q = 0; q < 4; q++) acc8(u[q], a);
        }
        if (i + 16 <= end) {
            int s0 = __ldg(&g_srclist[i + qid]);
            int s1 = __ldg(&g_srclist[i + 8 + qid]);
            uint4 u0 = __ldg(yrow + (size_t)s0 * 4 + l4);
            uint4 u1 = __ldg(yrow + (size_t)s1 * 4 + l4);
            acc8(u0, a); acc8(u1, a);
            i += 16;
        }
        if (i + 8 <= end) {
            int s0 = __ldg(&g_srclist[i + qid]);
            uint4 u0 = __ldg(yrow + (size_t)s0 * 4 + l4);
            acc8(u0, a);
            i += 8;
        }
        int rem = end - i;
        if (qid < rem) {
            int s0 = __ldg(&g_srclist[i + qid]);
            uint4 u0 = __ldg(yrow + (size_t)s0 * 4 + l4);
            acc8(u0, a);
        }
        // combine the 8 edge-groups (lane bits 2,3,4)
        #pragma unroll
        for (int c = 0; c < 8; c++) {
            a[c] += __shfl_xor_sync(0xFFFFFFFFu, a[c], 4);
            a[c] += __shfl_xor_sync(0xFFFFFFFFu, a[c], 8);
            a[c] += __shfl_xor_sync(0xFFFFFFFFu, a[c], 16);
        }
        float invd = 1.0f / fmaxf((float)(end - start), 1.0f);
        float4 r2a = __ldg((const float4*)(g_r2 + (size_t)node * 32) + 2 * l4);
        float4 r2b = __ldg((const float4*)(g_r2 + (size_t)node * 32) + 2 * l4 + 1);
        float dot =
            fmaxf(a[0] * invd + b2a.x + r2a.x, 0.0f) * wla.x +
            fmaxf(a[1] * invd + b2a.y + r2a.y, 0.0f) * wla.y +
            fmaxf(a[2] * invd + b2a.z + r2a.z, 0.0f) * wla.z +
            fmaxf(a[3] * invd + b2a.w + r2a.w, 0.0f) * wla.w +
            fmaxf(a[4] * invd + b2b.x + r2b.x, 0.0f) * wlb.x +
            fmaxf(a[5] * invd + b2b.y + r2b.y, 0.0f) * wlb.y +
            fmaxf(a[6] * invd + b2b.z + r2b.z, 0.0f) * wlb.z +
            fmaxf(a[7] * invd + b2b.w + r2b.w, 0.0f) * wlb.w;
        dot += __shfl_xor_sync(0xFFFFFFFFu, dot, 1);
        dot += __shfl_xor_sync(0xFFFFFFFFu, dot, 2);
        if (lane == 0) out[node] = dot + blv;
    }
}

// ---------------- launch (pre1 forked onto a side stream, overlapping CSR build) ----------------
extern "C" void kernel_launch(void* const* d_in, const int* in_sizes, int n_in,
                              void* d_out, int out_size) {
    const float* x    = (const float*)d_in[0];
    const void*  ei   = d_in[1];
    const float* W1l  = (const float*)d_in[2];
    const float* b1   = (const float*)d_in[3];
    const float* W1r  = (const float*)d_in[4];
    const float* W2l  = (const float*)d_in[5];
    const float* b2   = (const float*)d_in[6];
    const float* W2r  = (const float*)d_in[7];
    const float* Wlin = (const float*)d_in[8];
    const float* blin = (const float*)d_in[9];
    float* out = (float*)d_out;

    static cudaStream_t s1 = 0;
    static cudaEvent_t ev0 = 0, ev1 = 0;
    static int setup = 0;
    if (!setup) {
        if (cudaStreamCreateWithFlags(&s1, cudaStreamNonBlocking) != cudaSuccess) s1 = 0;
        if (s1) {
            cudaEventCreateWithFlags(&ev0, cudaEventDisableTiming);
            cudaEventCreateWithFlags(&ev1, cudaEventDisableTiming);
        }
        setup = 1;
    }

    if (s1) {
        // fork: pre1 runs concurrently with the CSR build
        cudaEventRecord(ev0, 0);
        cudaStreamWaitEvent(s1, ev0, 0);
        pre1_k<<<592, 256, 0, s1>>>(x, W1l, b1, W1r);
        cudaEventRecord(ev1, s1);
    } else {
        pre1_k<<<592, 256>>>(x, W1l, b1, W1r);
    }

    init_k<<<(N_NODES + 255) / 256, 256>>>((const long long*)ei);
    hist_k<<<(E_EDGES / 4 + 255) / 256, 256>>>(ei);
    blocksum_k<<<SCAN_BLOCKS, 256>>>();
    scan_k2<<<SCAN_BLOCKS, 256>>>();
    fill_k<<<(E_EDGES / 4 + 255) / 256, 256>>>(ei);

    if (s1) cudaStreamWaitEvent(0, ev1, 0);   // join before consuming z1/r1
    fused1_k<<<1184, 256>>>(W2l, W2r);
    fused2_k<<<1184, 256>>>(b2, Wlin, blin, out);
}